// round 1
// baseline (speedup 1.0000x reference)
#include <cuda_runtime.h>
#include <cuda_bf16.h>
#include <math.h>

// Problem constants
#define Bq   8
#define Nq   2048
#define Dq   1024
#define Eq   16
#define Sq   64
#define ESq  1024   // E*S
#define EPSq 1e-5f

// ---------------- scratch (device globals, allocation-free) ----------------
__device__ float g_w  [(size_t)Bq * Nq * ESq];   // weights  [B,N,ES]  64 MB
__device__ float g_dsp[(size_t)Bq * Nq * ESq];   // dispatch [B,N,ES]  64 MB
__device__ float g_cmb[(size_t)Bq * Nq * ESq];   // combine  [B,N,ES]  64 MB
__device__ float g_xin[(size_t)Bq * Eq * Sq * Dq]; // 32 MB
__device__ float g_h  [(size_t)Bq * Eq * Sq * Dq]; // 32 MB
__device__ float g_x2 [(size_t)Bq * Eq * Sq * Dq]; // 32 MB
__device__ float g_y  [(size_t)Bq * Eq * Sq * Dq]; // 32 MB

// ---------------- generic batched SGEMM ----------------
// C[z] = op(A[z]) * B[z%bMod]  (+ bias[z%bMod])  (+ res[z])
// op(A) = A        (TRANSA=0): A is [M,K], row stride lda
// op(A) = A^T      (TRANSA=1): A is [K,M], row stride lda
// B is [K,N] row stride ldb. C is [M,N] row stride ldc.
// EPI: 0 = none, 1 = +bias[col], 2 = +bias[col] + res[row,col]
template<int BM, int BN, int BK, int TM, int TN, int TRANSA, int EPI>
__global__ void sgemm_k(const float* __restrict__ Ab, const float* __restrict__ Bb,
                        const float* __restrict__ biasb, const float* __restrict__ resb,
                        float* __restrict__ Cb,
                        int K, int lda, int ldb, int ldc,
                        size_t sA, size_t sB, size_t sC, int bMod, size_t sBias)
{
    constexpr int THREADS = (BM / TM) * (BN / TN);

    const int z = blockIdx.z;
    const float* A = Ab + (size_t)z * sA;
    const float* B = Bb + (size_t)(z % bMod) * sB;
    float*       C = Cb + (size_t)z * sC;
    const float* bias = (EPI >= 1) ? (biasb + (size_t)(z % bMod) * sBias) : nullptr;
    const float* res  = (EPI == 2) ? (resb  + (size_t)z * sC) : nullptr;

    const int m0 = blockIdx.y * BM;
    const int n0 = blockIdx.x * BN;

    __shared__ float As[BK][BM];
    __shared__ float Bs[BK][BN];

    const int tid = threadIdx.x;
    const int tx  = tid % (BN / TN);
    const int ty  = tid / (BN / TN);

    float acc[TM][TN];
#pragma unroll
    for (int i = 0; i < TM; i++)
#pragma unroll
        for (int j = 0; j < TN; j++) acc[i][j] = 0.f;

    for (int k0 = 0; k0 < K; k0 += BK) {
        // ---- load A tile into As[k][m]
        if (TRANSA) {
#pragma unroll
            for (int i = tid; i < BK * BM; i += THREADS) {
                int k = i / BM, m = i % BM;
                As[k][m] = A[(size_t)(k0 + k) * lda + m0 + m];
            }
        } else {
#pragma unroll
            for (int i = tid; i < BM * BK; i += THREADS) {
                int m = i / BK, k = i % BK;
                As[k][m] = A[(size_t)(m0 + m) * lda + k0 + k];
            }
        }
        // ---- load B tile into Bs[k][n]  (fully coalesced)
#pragma unroll
        for (int i = tid; i < BK * BN; i += THREADS) {
            int k = i / BN, n = i % BN;
            Bs[k][n] = B[(size_t)(k0 + k) * ldb + n0 + n];
        }
        __syncthreads();

#pragma unroll
        for (int k = 0; k < BK; k++) {
            float a[TM], bv[TN];
#pragma unroll
            for (int i = 0; i < TM / 4; i++) {
                float4 v = *reinterpret_cast<const float4*>(&As[k][ty * TM + 4 * i]);
                a[4 * i] = v.x; a[4 * i + 1] = v.y; a[4 * i + 2] = v.z; a[4 * i + 3] = v.w;
            }
#pragma unroll
            for (int j = 0; j < TN / 4; j++) {
                float4 v = *reinterpret_cast<const float4*>(&Bs[k][tx * TN + 4 * j]);
                bv[4 * j] = v.x; bv[4 * j + 1] = v.y; bv[4 * j + 2] = v.z; bv[4 * j + 3] = v.w;
            }
#pragma unroll
            for (int i = 0; i < TM; i++)
#pragma unroll
                for (int j = 0; j < TN; j++)
                    acc[i][j] = fmaf(a[i], bv[j], acc[i][j]);
        }
        __syncthreads();
    }

    // ---- epilogue
#pragma unroll
    for (int i = 0; i < TM; i++) {
        const int row = m0 + ty * TM + i;
#pragma unroll
        for (int j = 0; j < TN; j++) {
            const int col = n0 + tx * TN + j;
            float v = acc[i][j];
            if (EPI >= 1) v += bias[col];
            if (EPI == 2) v += res[(size_t)row * ldc + col];
            C[(size_t)row * ldc + col] = v;
        }
    }
}

// ---------------- dispatch softmax: softmax over tokens (axis n) ----------------
// w, out: [B, N, ES]. One block handles 32 consecutive es-columns of one batch.
__global__ void dispatch_softmax_k(const float* __restrict__ w, float* __restrict__ out)
{
    const int b    = blockIdx.y;
    const int lane = threadIdx.x & 31;
    const int grp  = threadIdx.x >> 5;            // 0..7
    const int col  = blockIdx.x * 32 + lane;

    const float* p = w   + (size_t)b * Nq * ESq + col;
    float*       o = out + (size_t)b * Nq * ESq + col;

    __shared__ float red[8][33];

    float mx = -1e30f;
    for (int n = grp; n < Nq; n += 8) mx = fmaxf(mx, p[(size_t)n * ESq]);
    red[grp][lane] = mx;
    __syncthreads();
    if (grp == 0) {
        float m = red[0][lane];
#pragma unroll
        for (int g = 1; g < 8; g++) m = fmaxf(m, red[g][lane]);
        red[0][lane] = m;
    }
    __syncthreads();
    const float m = red[0][lane];
    __syncthreads();

    float s = 0.f;
    for (int n = grp; n < Nq; n += 8) s += __expf(p[(size_t)n * ESq] - m);
    red[grp][lane] = s;
    __syncthreads();
    if (grp == 0) {
        float t = red[0][lane];
#pragma unroll
        for (int g = 1; g < 8; g++) t += red[g][lane];
        red[0][lane] = t;
    }
    __syncthreads();
    const float inv = 1.f / red[0][lane];

    for (int n = grp; n < Nq; n += 8)
        o[(size_t)n * ESq] = __expf(p[(size_t)n * ESq] - m) * inv;
}

// ---------------- combine softmax: row softmax over ES=1024 ----------------
__global__ void row_softmax_k(const float* __restrict__ w, float* __restrict__ out)
{
    const size_t r = blockIdx.x;
    const float* p = w   + r * ESq;
    float*       o = out + r * ESq;
    const int tid = threadIdx.x;

    __shared__ float buf[256];

    float v[4];
    float mx = -1e30f;
#pragma unroll
    for (int j = 0; j < 4; j++) { v[j] = p[tid + 256 * j]; mx = fmaxf(mx, v[j]); }
    buf[tid] = mx;
    __syncthreads();
    for (int off = 128; off > 0; off >>= 1) {
        if (tid < off) buf[tid] = fmaxf(buf[tid], buf[tid + off]);
        __syncthreads();
    }
    const float m = buf[0];
    __syncthreads();

    float s = 0.f;
#pragma unroll
    for (int j = 0; j < 4; j++) { v[j] = __expf(v[j] - m); s += v[j]; }
    buf[tid] = s;
    __syncthreads();
    for (int off = 128; off > 0; off >>= 1) {
        if (tid < off) buf[tid] += buf[tid + off];
        __syncthreads();
    }
    const float inv = 1.f / buf[0];
#pragma unroll
    for (int j = 0; j < 4; j++) o[tid + 256 * j] = v[j] * inv;
}

// ---------------- LN + relu + residual: x2 = xin + relu(LN(h)*g + be) ----------------
__global__ void ln_relu_k(const float* __restrict__ h, const float* __restrict__ xin,
                          const float* __restrict__ g, const float* __restrict__ be,
                          float* __restrict__ x2)
{
    const int r = blockIdx.x;                 // row in [0, B*E*S)
    const int e = (r / Sq) % Eq;
    const float* hr = h   + (size_t)r * Dq;
    const float* xr = xin + (size_t)r * Dq;
    float*       orr = x2 + (size_t)r * Dq;
    const int tid = threadIdx.x;

    __shared__ float rs[256], rs2[256];

    float v[4];
    float s = 0.f, s2 = 0.f;
#pragma unroll
    for (int j = 0; j < 4; j++) {
        v[j] = hr[tid + 256 * j];
        s += v[j]; s2 += v[j] * v[j];
    }
    rs[tid] = s; rs2[tid] = s2;
    __syncthreads();
    for (int off = 128; off > 0; off >>= 1) {
        if (tid < off) { rs[tid] += rs[tid + off]; rs2[tid] += rs2[tid + off]; }
        __syncthreads();
    }
    const float mean = rs[0] * (1.f / Dq);
    const float var  = rs2[0] * (1.f / Dq) - mean * mean;
    const float rstd = rsqrtf(var + EPSq);

#pragma unroll
    for (int j = 0; j < 4; j++) {
        const int d = tid + 256 * j;
        const float ln = (v[j] - mean) * rstd * g[(size_t)e * Dq + d] + be[(size_t)e * Dq + d];
        orr[d] = xr[d] + fmaxf(ln, 0.f);
    }
}

// ---------------- launch ----------------
extern "C" void kernel_launch(void* const* d_in, const int* in_sizes, int n_in,
                              void* d_out, int out_size)
{
    const float* x   = (const float*)d_in[0];
    const float* phi = (const float*)d_in[1];
    const float* W1  = (const float*)d_in[2];
    const float* b1  = (const float*)d_in[3];
    const float* g1  = (const float*)d_in[4];
    const float* be1 = (const float*)d_in[5];
    const float* W2  = (const float*)d_in[6];
    const float* b2  = (const float*)d_in[7];
    float* out = (float*)d_out;

    float *w, *dsp, *cmb, *xin, *h, *x2, *y;
    cudaGetSymbolAddress((void**)&w,   g_w);
    cudaGetSymbolAddress((void**)&dsp, g_dsp);
    cudaGetSymbolAddress((void**)&cmb, g_cmb);
    cudaGetSymbolAddress((void**)&xin, g_xin);
    cudaGetSymbolAddress((void**)&h,   g_h);
    cudaGetSymbolAddress((void**)&x2,  g_x2);
    cudaGetSymbolAddress((void**)&y,   g_y);

    // K1: weights[b] = x[b] @ phi          [2048,1024] = [2048,1024]@[1024,1024]
    sgemm_k<128,128,8,8,8,0,0><<<dim3(ESq/128, Nq/128, Bq), 256>>>(
        x, phi, nullptr, nullptr, w,
        Dq, Dq, ESq, ESq,
        (size_t)Nq * Dq, 0, (size_t)Nq * ESq, 1, 0);

    // K2: dispatch = softmax over tokens
    dispatch_softmax_k<<<dim3(ESq/32, Bq), 256>>>(w, dsp);

    // K3: xin[b] = dispatch[b]^T @ x[b]    [1024,1024] = [2048,1024]^T @ [2048,1024]
    sgemm_k<128,128,8,8,8,1,0><<<dim3(Dq/128, ESq/128, Bq), 256>>>(
        dsp, x, nullptr, nullptr, xin,
        Nq, ESq, Dq, Dq,
        (size_t)Nq * ESq, (size_t)Nq * Dq, (size_t)ESq * Dq, Bq, 0);

    // K4: h[b,e] = xin[b,e] @ W1[e] + b1[e]   [64,1024] per (b,e)
    sgemm_k<64,64,8,4,4,0,1><<<dim3(Dq/64, Sq/64, Bq*Eq), 256>>>(
        xin, W1, b1, nullptr, h,
        Dq, Dq, Dq, Dq,
        (size_t)Sq * Dq, (size_t)Dq * Dq, (size_t)Sq * Dq, Eq, (size_t)Dq);

    // K5: x2 = xin + relu(LN(h))
    ln_relu_k<<<Bq*Eq*Sq, 256>>>(h, xin, g1, be1, x2);

    // K6: y[b,e] = x2[b,e] + x2[b,e] @ W2[e] + b2[e]
    sgemm_k<64,64,8,4,4,0,2><<<dim3(Dq/64, Sq/64, Bq*Eq), 256>>>(
        x2, W2, b2, x2, y,
        Dq, Dq, Dq, Dq,
        (size_t)Sq * Dq, (size_t)Dq * Dq, (size_t)Sq * Dq, Eq, (size_t)Dq);

    // K7: combine = row softmax of weights
    row_softmax_k<<<Bq*Nq, 256>>>(w, cmb);

    // K8: out[b] = combine[b] @ y[b]       [2048,1024] = [2048,1024]@[1024,1024]
    sgemm_k<128,128,8,8,8,0,0><<<dim3(Dq/128, Nq/128, Bq), 256>>>(
        cmb, y, nullptr, nullptr, out,
        ESq, ESq, Dq, Dq,
        (size_t)Nq * ESq, (size_t)Eq * Sq * Dq, (size_t)Nq * Dq, Bq, 0);
}

// round 2
// speedup vs baseline: 1.4285x; 1.4285x over previous
#include <cuda_runtime.h>
#include <cuda_bf16.h>
#include <math.h>

typedef unsigned long long ULL;

// Problem constants
#define Bq   8
#define Nq   2048
#define Dq   1024
#define Eq   16
#define Sq   64
#define ESq  1024   // E*S
#define EPSq 1e-5f

// ---------------- scratch (device globals, allocation-free) ----------------
__device__ float g_w  [(size_t)Bq * Nq * ESq];
__device__ float g_dsp[(size_t)Bq * Nq * ESq];
__device__ float g_cmb[(size_t)Bq * Nq * ESq];
__device__ float g_xin[(size_t)Bq * Eq * Sq * Dq];
__device__ float g_h  [(size_t)Bq * Eq * Sq * Dq];
__device__ float g_x2 [(size_t)Bq * Eq * Sq * Dq];
__device__ float g_y  [(size_t)Bq * Eq * Sq * Dq];

// ---------------- packed f32x2 helpers ----------------
__device__ __forceinline__ void ffma2(ULL& acc, ULL a, ULL b) {
    asm("fma.rn.f32x2 %0, %1, %2, %0;" : "+l"(acc) : "l"(a), "l"(b));
}
__device__ __forceinline__ ULL dup2(float v) {
    ULL r;
    asm("mov.b64 %0, {%1, %1};" : "=l"(r) : "r"(__float_as_uint(v)));
    return r;
}

// ---------------- batched SGEMM with FFMA2 + row remap ----------------
// C[z] = op(A[z]) * B[z % bMod] (+ bias) (+ res)
// TRANSA=0: A rows addressed via (r>>6)*aRowBlk + (r&63)*lda  (dense: aRowBlk=64*lda)
// TRANSA=1: A is [K, M], dense, row stride lda.
// C rows addressed via (r>>6)*cRowBlk + (r&63)*ldc            (dense: cRowBlk=64*ldc)
// EPI: 0=none, 1=+bias[col], 2=+bias[col]+res[row,col] (res uses C mapping)
template<int BM, int BN, int BK, int TM, int TN, int TRANSA, int EPI>
__global__ void __launch_bounds__(256)
gemm2_k(const float* __restrict__ Ab, const float* __restrict__ Bb,
        const float* __restrict__ biasb, const float* __restrict__ resb,
        float* __restrict__ Cb,
        int K, int lda, int ldb, int ldc,
        size_t sA, size_t sB, size_t sC, int bMod, size_t sBias,
        size_t aRowBlk, size_t cRowBlk)
{
    const int z = blockIdx.z;
    const float* A = Ab + (size_t)z * sA;
    const float* B = Bb + (size_t)(z % bMod) * sB;
    float*       C = Cb + (size_t)z * sC;
    const float* bias = (EPI >= 1) ? (biasb + (size_t)(z % bMod) * sBias) : nullptr;
    const float* res  = (EPI == 2) ? (resb  + (size_t)z * sC) : nullptr;

    const int m0 = blockIdx.y * BM;
    const int n0 = blockIdx.x * BN;

    __shared__ float As[2][BK][BM];
    __shared__ float Bs[2][BK][BN];

    const int tid = threadIdx.x;

    // B tile load map: float4, coalesced
    const int bk = tid / (BN / 4);
    const int bn = (tid % (BN / 4)) * 4;
    // A tile load map
    int am, ak;
    if (TRANSA) { ak = tid / (BM / 4); am = (tid % (BM / 4)) * 4; }
    else        { am = tid / 2;        ak = (tid % 2) * 4;        }

    float4 ra, rb;

    auto ldg_tile = [&](int k0) {
        rb = *reinterpret_cast<const float4*>(&B[(size_t)(k0 + bk) * ldb + n0 + bn]);
        if (TRANSA) {
            ra = *reinterpret_cast<const float4*>(&A[(size_t)(k0 + ak) * lda + m0 + am]);
        } else {
            const int r = m0 + am;
            const size_t off = ((size_t)(r >> 6)) * aRowBlk + (size_t)(r & 63) * lda;
            ra = *reinterpret_cast<const float4*>(&A[off + k0 + ak]);
        }
    };
    auto sts_tile = [&](int buf) {
        *reinterpret_cast<float4*>(&Bs[buf][bk][bn]) = rb;
        if (TRANSA) {
            *reinterpret_cast<float4*>(&As[buf][ak][am]) = ra;
        } else {
            As[buf][ak + 0][am] = ra.x;
            As[buf][ak + 1][am] = ra.y;
            As[buf][ak + 2][am] = ra.z;
            As[buf][ak + 3][am] = ra.w;
        }
    };

    const int ty = tid / (BN / TN);
    const int tx = tid % (BN / TN);

    ULL acc[TM / 2][TN];
#pragma unroll
    for (int i = 0; i < TM / 2; i++)
#pragma unroll
        for (int j = 0; j < TN; j++) acc[i][j] = 0ULL;

    const int nTiles = K / BK;

    ldg_tile(0);
    sts_tile(0);
    if (nTiles > 1) ldg_tile(BK);
    __syncthreads();

    for (int t = 0; t < nTiles; ++t) {
        const int buf = t & 1;
        if (t + 1 < nTiles) sts_tile(buf ^ 1);          // regs hold tile t+1
        if (t + 2 < nTiles) ldg_tile((t + 2) * BK);     // prefetch tile t+2

#pragma unroll
        for (int k = 0; k < BK; k++) {
            // A pairs (m, m+1) load natively as 64-bit packed operands
            const ulonglong2* ap = reinterpret_cast<const ulonglong2*>(&As[buf][k][ty * TM]);
            ulonglong2 aA = ap[0], aB = ap[1];
            ULL a2[TM / 2] = { aA.x, aA.y, aB.x, aB.y };

            const float4* bp = reinterpret_cast<const float4*>(&Bs[buf][k][tx * TN]);
            float4 b0 = bp[0], b1 = bp[1];
            ULL b2[TN];
            b2[0] = dup2(b0.x); b2[1] = dup2(b0.y); b2[2] = dup2(b0.z); b2[3] = dup2(b0.w);
            b2[4] = dup2(b1.x); b2[5] = dup2(b1.y); b2[6] = dup2(b1.z); b2[7] = dup2(b1.w);

#pragma unroll
            for (int i = 0; i < TM / 2; i++)
#pragma unroll
                for (int j = 0; j < TN; j++)
                    ffma2(acc[i][j], a2[i], b2[j]);
        }
        if (t + 1 < nTiles) __syncthreads();
    }

    // ---- epilogue
#pragma unroll
    for (int i = 0; i < TM / 2; i++) {
        const int r0 = m0 + ty * TM + 2 * i;
        const size_t off0 = ((size_t)(r0 >> 6)) * cRowBlk + (size_t)(r0 & 63) * ldc;
        const size_t off1 = ((size_t)((r0 + 1) >> 6)) * cRowBlk + (size_t)((r0 + 1) & 63) * ldc;
#pragma unroll
        for (int j = 0; j < TN; j++) {
            const int col = n0 + tx * TN + j;
            float2 v = *reinterpret_cast<float2*>(&acc[i][j]);
            if (EPI >= 1) { const float bb = bias[col]; v.x += bb; v.y += bb; }
            if (EPI == 2) { v.x += res[off0 + col]; v.y += res[off1 + col]; }
            C[off0 + col] = v.x;
            C[off1 + col] = v.y;
        }
    }
}

// ---------------- dispatch softmax: softmax over tokens (axis n) ----------------
__global__ void dispatch_softmax_k(const float* __restrict__ w, float* __restrict__ out)
{
    const int b    = blockIdx.y;
    const int lane = threadIdx.x & 31;
    const int grp  = threadIdx.x >> 5;
    const int col  = blockIdx.x * 32 + lane;

    const float* p = w   + (size_t)b * Nq * ESq + col;
    float*       o = out + (size_t)b * Nq * ESq + col;

    __shared__ float red[8][33];

    float mx = -1e30f;
    for (int n = grp; n < Nq; n += 8) mx = fmaxf(mx, p[(size_t)n * ESq]);
    red[grp][lane] = mx;
    __syncthreads();
    if (grp == 0) {
        float m = red[0][lane];
#pragma unroll
        for (int g = 1; g < 8; g++) m = fmaxf(m, red[g][lane]);
        red[0][lane] = m;
    }
    __syncthreads();
    const float m = red[0][lane];
    __syncthreads();

    float s = 0.f;
    for (int n = grp; n < Nq; n += 8) s += __expf(p[(size_t)n * ESq] - m);
    red[grp][lane] = s;
    __syncthreads();
    if (grp == 0) {
        float t = red[0][lane];
#pragma unroll
        for (int g = 1; g < 8; g++) t += red[g][lane];
        red[0][lane] = t;
    }
    __syncthreads();
    const float inv = 1.f / red[0][lane];

    for (int n = grp; n < Nq; n += 8)
        o[(size_t)n * ESq] = __expf(p[(size_t)n * ESq] - m) * inv;
}

// ---------------- combine softmax: row softmax over ES=1024 ----------------
__global__ void row_softmax_k(const float* __restrict__ w, float* __restrict__ out)
{
    const size_t r = blockIdx.x;
    const float* p = w   + r * ESq;
    float*       o = out + r * ESq;
    const int tid = threadIdx.x;

    __shared__ float buf[256];

    float v[4];
    float mx = -1e30f;
#pragma unroll
    for (int j = 0; j < 4; j++) { v[j] = p[tid + 256 * j]; mx = fmaxf(mx, v[j]); }
    buf[tid] = mx;
    __syncthreads();
    for (int off = 128; off > 0; off >>= 1) {
        if (tid < off) buf[tid] = fmaxf(buf[tid], buf[tid + off]);
        __syncthreads();
    }
    const float m = buf[0];
    __syncthreads();

    float s = 0.f;
#pragma unroll
    for (int j = 0; j < 4; j++) { v[j] = __expf(v[j] - m); s += v[j]; }
    buf[tid] = s;
    __syncthreads();
    for (int off = 128; off > 0; off >>= 1) {
        if (tid < off) buf[tid] += buf[tid + off];
        __syncthreads();
    }
    const float inv = 1.f / buf[0];
#pragma unroll
    for (int j = 0; j < 4; j++) o[tid + 256 * j] = v[j] * inv;
}

// ---------------- LN + relu + residual ----------------
__global__ void ln_relu_k(const float* __restrict__ h, const float* __restrict__ xin,
                          const float* __restrict__ g, const float* __restrict__ be,
                          float* __restrict__ x2)
{
    const int r = blockIdx.x;
    const int e = (r / Sq) % Eq;
    const float* hr = h   + (size_t)r * Dq;
    const float* xr = xin + (size_t)r * Dq;
    float*       orr = x2 + (size_t)r * Dq;
    const int tid = threadIdx.x;

    __shared__ float rs[256], rs2[256];

    float v[4];
    float s = 0.f, s2 = 0.f;
#pragma unroll
    for (int j = 0; j < 4; j++) {
        v[j] = hr[tid + 256 * j];
        s += v[j]; s2 += v[j] * v[j];
    }
    rs[tid] = s; rs2[tid] = s2;
    __syncthreads();
    for (int off = 128; off > 0; off >>= 1) {
        if (tid < off) { rs[tid] += rs[tid + off]; rs2[tid] += rs2[tid + off]; }
        __syncthreads();
    }
    const float mean = rs[0] * (1.f / Dq);
    const float var  = rs2[0] * (1.f / Dq) - mean * mean;
    const float rstd = rsqrtf(var + EPSq);

#pragma unroll
    for (int j = 0; j < 4; j++) {
        const int d = tid + 256 * j;
        const float ln = (v[j] - mean) * rstd * g[(size_t)e * Dq + d] + be[(size_t)e * Dq + d];
        orr[d] = xr[d] + fmaxf(ln, 0.f);
    }
}

// ---------------- launch ----------------
extern "C" void kernel_launch(void* const* d_in, const int* in_sizes, int n_in,
                              void* d_out, int out_size)
{
    const float* x   = (const float*)d_in[0];
    const float* phi = (const float*)d_in[1];
    const float* W1  = (const float*)d_in[2];
    const float* b1  = (const float*)d_in[3];
    const float* g1  = (const float*)d_in[4];
    const float* be1 = (const float*)d_in[5];
    const float* W2  = (const float*)d_in[6];
    const float* b2  = (const float*)d_in[7];
    float* out = (float*)d_out;

    float *w, *dsp, *cmb, *xin, *h, *x2, *y;
    cudaGetSymbolAddress((void**)&w,   g_w);
    cudaGetSymbolAddress((void**)&dsp, g_dsp);
    cudaGetSymbolAddress((void**)&cmb, g_cmb);
    cudaGetSymbolAddress((void**)&xin, g_xin);
    cudaGetSymbolAddress((void**)&h,   g_h);
    cudaGetSymbolAddress((void**)&x2,  g_x2);
    cudaGetSymbolAddress((void**)&y,   g_y);

    const size_t EXP = (size_t)Eq * Sq * Dq;   // batch stride of [b,e,s,d] tensors

    // K1: weights[b] = x[b] @ phi   [2048x1024] @ [1024x1024], batch 8
    gemm2_k<128,128,8,8,8,0,0><<<dim3(ESq/128, Nq/128, Bq), 256>>>(
        x, phi, nullptr, nullptr, w,
        Dq, Dq, ESq, ESq,
        (size_t)Nq * Dq, 0, (size_t)Nq * ESq, 1, 0,
        (size_t)64 * Dq, (size_t)64 * ESq);

    // K2: dispatch = softmax over tokens
    dispatch_softmax_k<<<dim3(ESq/32, Bq), 256>>>(w, dsp);

    // K3: xin[b] = dispatch[b]^T @ x[b]   [1024x1024] = [2048x1024]^T @ [2048x1024]
    gemm2_k<128,128,8,8,8,1,0><<<dim3(Dq/128, ESq/128, Bq), 256>>>(
        dsp, x, nullptr, nullptr, xin,
        Nq, ESq, Dq, Dq,
        (size_t)Nq * ESq, (size_t)Nq * Dq, (size_t)ESq * Dq, Bq, 0,
        0, (size_t)64 * Dq);

    // K4: per-expert h = xin_e @ W1[e] + b1[e]   [512x1024] @ [1024x1024], z = e
    gemm2_k<128,128,8,8,8,0,1><<<dim3(Dq/128, (Bq*Sq)/128, Eq), 256>>>(
        xin, W1, b1, nullptr, h,
        Dq, Dq, Dq, Dq,
        (size_t)Sq * Dq, (size_t)Dq * Dq, (size_t)Sq * Dq, Eq, (size_t)Dq,
        EXP, EXP);

    // K5: x2 = xin + relu(LN(h))
    ln_relu_k<<<Bq*Eq*Sq, 256>>>(h, xin, g1, be1, x2);

    // K6: per-expert y = x2 + x2_e @ W2[e] + b2[e]
    gemm2_k<128,128,8,8,8,0,2><<<dim3(Dq/128, (Bq*Sq)/128, Eq), 256>>>(
        x2, W2, b2, x2, y,
        Dq, Dq, Dq, Dq,
        (size_t)Sq * Dq, (size_t)Dq * Dq, (size_t)Sq * Dq, Eq, (size_t)Dq,
        EXP, EXP);

    // K7: combine = row softmax of weights
    row_softmax_k<<<Bq*Nq, 256>>>(w, cmb);

    // K8: out[b] = combine[b] @ y[b]   [2048x1024] @ [1024x1024], batch 8
    gemm2_k<128,128,8,8,8,0,0><<<dim3(Dq/128, Nq/128, Bq), 256>>>(
        cmb, y, nullptr, nullptr, out,
        ESq, ESq, Dq, Dq,
        (size_t)Nq * ESq, EXP, (size_t)Nq * Dq, Bq, 0,
        (size_t)64 * ESq, (size_t)64 * Dq);
}

// round 4
// speedup vs baseline: 3.2798x; 2.2959x over previous
#include <cuda_runtime.h>
#include <cuda_bf16.h>
#include <math.h>
#include <stdint.h>

typedef __nv_bfloat16 bf16;

#define Bq   8
#define Nq   2048
#define Dq   1024
#define Eq   16
#define Sq   64
#define ESq  1024
#define EPSq 1e-5f

// ---------------- fp32 scratch ----------------
__device__ __align__(16) float g_w  [(size_t)Bq * Nq * ESq];
__device__ __align__(16) float g_dsp[(size_t)Bq * Nq * ESq];
__device__ __align__(16) float g_xin[(size_t)Bq * Eq * Sq * Dq];
__device__ __align__(16) float g_h  [(size_t)Bq * Eq * Sq * Dq];
__device__ __align__(16) float g_x2 [(size_t)Bq * Eq * Sq * Dq];
__device__ __align__(16) float g_y  [(size_t)Bq * Eq * Sq * Dq];

// ---------------- bf16 split scratch ----------------
__device__ __align__(16) bf16 g_xs_h [(size_t)Bq * Nq * Dq],  g_xs_l [(size_t)Bq * Nq * Dq];
__device__ __align__(16) bf16 g_xT_h [(size_t)Bq * Dq * Nq],  g_xT_l [(size_t)Bq * Dq * Nq];
__device__ __align__(16) bf16 g_phiT_h[(size_t)ESq * Dq],     g_phiT_l[(size_t)ESq * Dq];
__device__ __align__(16) bf16 g_W1T_h[(size_t)Eq * Dq * Dq],  g_W1T_l[(size_t)Eq * Dq * Dq];
__device__ __align__(16) bf16 g_W2T_h[(size_t)Eq * Dq * Dq],  g_W2T_l[(size_t)Eq * Dq * Dq];
__device__ __align__(16) bf16 g_dspT_h[(size_t)Bq * ESq * Nq], g_dspT_l[(size_t)Bq * ESq * Nq];
__device__ __align__(16) bf16 g_xinS_h[(size_t)Bq * Eq * Sq * Dq], g_xinS_l[(size_t)Bq * Eq * Sq * Dq];
__device__ __align__(16) bf16 g_x2S_h[(size_t)Bq * Eq * Sq * Dq],  g_x2S_l[(size_t)Bq * Eq * Sq * Dq];
__device__ __align__(16) bf16 g_yT_h [(size_t)Bq * Dq * ESq],  g_yT_l [(size_t)Bq * Dq * ESq];
__device__ __align__(16) bf16 g_cmb_h[(size_t)Bq * Nq * ESq],  g_cmb_l[(size_t)Bq * Nq * ESq];

// ================= mma.sync GEMM =================
#define BM 128
#define BN 128
#define BK 32
#define PADE 40                    // bf16 elems per smem row (80 B, 16B-aligned, conflict-free)
#define OFF_AH 0
#define OFF_AL 10240
#define OFF_BH 20480
#define OFF_BL 30720
#define STAGE  40960
#define SMEM_DYN (2 * STAGE)

__device__ __forceinline__ uint32_t s2u(const void* p) {
    uint32_t a;
    asm("{ .reg .u64 t; cvta.to.shared.u64 t, %1; cvt.u32.u64 %0, t; }" : "=r"(a) : "l"(p));
    return a;
}
__device__ __forceinline__ void cpa16(uint32_t dst, const void* src) {
    asm volatile("cp.async.cg.shared.global [%0], [%1], 16;" :: "r"(dst), "l"(src));
}
__device__ __forceinline__ void ldm_x4(uint32_t* r, uint32_t a) {
    asm volatile("ldmatrix.sync.aligned.m8n8.x4.shared.b16 {%0,%1,%2,%3}, [%4];"
                 : "=r"(r[0]), "=r"(r[1]), "=r"(r[2]), "=r"(r[3]) : "r"(a));
}
__device__ __forceinline__ void ldm_x2(uint32_t* r, uint32_t a) {
    asm volatile("ldmatrix.sync.aligned.m8n8.x2.shared.b16 {%0,%1}, [%2];"
                 : "=r"(r[0]), "=r"(r[1]) : "r"(a));
}
__device__ __forceinline__ void mma16816(float* c, const uint32_t* a, const uint32_t* b) {
    asm volatile(
        "mma.sync.aligned.m16n8k16.row.col.f32.bf16.bf16.f32 "
        "{%0,%1,%2,%3}, {%4,%5,%6,%7}, {%8,%9}, {%0,%1,%2,%3};"
        : "+f"(c[0]), "+f"(c[1]), "+f"(c[2]), "+f"(c[3])
        : "r"(a[0]), "r"(a[1]), "r"(a[2]), "r"(a[3]), "r"(b[0]), "r"(b[1]));
}

// C[z] = Asplit[z] @ Bsplit[z%bMod]^T (+bias) (+res); A,B bf16 hi/lo, K-major.
// A rows: off = (r>>6)*aRowBlk + (r&63)*lda; C rows likewise via cRowBlk.
// EPI: 0 none, 1 +bias[col], 2 +bias[col]+res. SPLIT: also emit bf16 hi/lo of C.
template<int EPI, int SPLIT>
__global__ void __launch_bounds__(256, 1)
mma_gemm_k(const bf16* __restrict__ Ahb, const bf16* __restrict__ Alb,
           const bf16* __restrict__ Bhb, const bf16* __restrict__ Blb,
           const float* __restrict__ biasb, const float* __restrict__ resb,
           float* __restrict__ Cb, bf16* __restrict__ Chb, bf16* __restrict__ Clb,
           int K, int lda, int ldb, int ldc,
           size_t sA, size_t sB, size_t sC, int bMod, size_t sBias,
           size_t aRowBlk, size_t cRowBlk)
{
    extern __shared__ char sm[];
    const uint32_t sb = s2u(sm);
    const int tid = threadIdx.x, wid = tid >> 5, lane = tid & 31;
    const int z = blockIdx.z;

    const bf16* Ah = Ahb + (size_t)z * sA;
    const bf16* Al = Alb + (size_t)z * sA;
    const bf16* Bh = Bhb + (size_t)(z % bMod) * sB;
    const bf16* Bl = Blb + (size_t)(z % bMod) * sB;

    const int m0 = blockIdx.y * BM;
    const int n0 = blockIdx.x * BN;

    // per-thread cp.async maps: 512 16B-chunks per operand-half, 2 per thread
    size_t aoff[2], boff[2];
    uint32_t adst[2], bdst[2];
#pragma unroll
    for (int i = 0; i < 2; i++) {
        const int idx = tid + i * 256;
        const int row = idx >> 2, kc = idx & 3;
        const int m = m0 + row;
        aoff[i] = ((size_t)(m >> 6)) * aRowBlk + (size_t)(m & 63) * lda + kc * 8;
        boff[i] = (size_t)(n0 + row) * ldb + kc * 8;
        adst[i] = bdst[i] = (uint32_t)(row * 80 + kc * 16);
    }

    auto load_stage = [&](int t, int buf) {
        const uint32_t stg = sb + buf * STAGE;
        const size_t ke = (size_t)t * BK;
#pragma unroll
        for (int i = 0; i < 2; i++) {
            cpa16(stg + OFF_AH + adst[i], Ah + aoff[i] + ke);
            cpa16(stg + OFF_AL + adst[i], Al + aoff[i] + ke);
            cpa16(stg + OFF_BH + bdst[i], Bh + boff[i] + ke);
            cpa16(stg + OFF_BL + bdst[i], Bl + boff[i] + ke);
        }
        asm volatile("cp.async.commit_group;" ::: "memory");
    };

    const int wm = (wid >> 2) * 64;     // warp M offset in tile
    const int wn = (wid & 3) * 32;      // warp N offset in tile

    float acc[4][4][4];
#pragma unroll
    for (int mi = 0; mi < 4; mi++)
#pragma unroll
        for (int ni = 0; ni < 4; ni++)
#pragma unroll
            for (int q = 0; q < 4; q++) acc[mi][ni][q] = 0.f;

    const int nt = K / BK;
    load_stage(0, 0);

    for (int t = 0; t < nt; t++) {
        if (t + 1 < nt) {
            load_stage(t + 1, (t + 1) & 1);
            asm volatile("cp.async.wait_group 1;" ::: "memory");
        } else {
            asm volatile("cp.async.wait_group 0;" ::: "memory");
        }
        __syncthreads();

        const uint32_t stg = sb + (t & 1) * STAGE;
#pragma unroll
        for (int ks = 0; ks < 2; ks++) {
            const int kb = ks * 16;
            uint32_t ah[4][4], al[4][4], bh[4][2], bl[4][2];
#pragma unroll
            for (int mi = 0; mi < 4; mi++) {
                const uint32_t ao =
                    (uint32_t)((wm + mi * 16 + (lane & 15)) * 80 + (kb + (lane >> 4) * 8) * 2);
                ldm_x4(ah[mi], stg + OFF_AH + ao);
                ldm_x4(al[mi], stg + OFF_AL + ao);
            }
#pragma unroll
            for (int ni = 0; ni < 4; ni++) {
                const uint32_t bo =
                    (uint32_t)((wn + ni * 8 + (lane & 7)) * 80 + (kb + ((lane >> 3) & 1) * 8) * 2);
                ldm_x2(bh[ni], stg + OFF_BH + bo);
                ldm_x2(bl[ni], stg + OFF_BL + bo);
            }
#pragma unroll
            for (int mi = 0; mi < 4; mi++)
#pragma unroll
                for (int ni = 0; ni < 4; ni++) {
                    mma16816(acc[mi][ni], ah[mi], bh[ni]);
                    mma16816(acc[mi][ni], al[mi], bh[ni]);
                    mma16816(acc[mi][ni], ah[mi], bl[ni]);
                }
        }
        __syncthreads();
    }

    // ---------------- epilogue (direct stores) ----------------
    float*       C  = Cb + (size_t)z * sC;
    bf16*        Ch = SPLIT ? (Chb + (size_t)z * sC) : nullptr;
    bf16*        Cl = SPLIT ? (Clb + (size_t)z * sC) : nullptr;
    const float* bias = (EPI >= 1) ? (biasb + (size_t)(z % bMod) * sBias) : nullptr;
    const float* res  = (EPI == 2) ? (resb  + (size_t)z * sC) : nullptr;

#pragma unroll
    for (int mi = 0; mi < 4; mi++) {
        const int mA = m0 + wm + mi * 16 + (lane >> 2);
        const int mB = mA + 8;
        const size_t coA = ((size_t)(mA >> 6)) * cRowBlk + (size_t)(mA & 63) * ldc;
        const size_t coB = ((size_t)(mB >> 6)) * cRowBlk + (size_t)(mB & 63) * ldc;
#pragma unroll
        for (int ni = 0; ni < 4; ni++) {
            const int col = n0 + wn + ni * 8 + (lane & 3) * 2;
            float2 v0 = make_float2(acc[mi][ni][0], acc[mi][ni][1]);
            float2 v1 = make_float2(acc[mi][ni][2], acc[mi][ni][3]);
            if (EPI >= 1) {
                const float2 bb = *reinterpret_cast<const float2*>(&bias[col]);
                v0.x += bb.x; v0.y += bb.y; v1.x += bb.x; v1.y += bb.y;
            }
            if (EPI == 2) {
                const float2 rA = *reinterpret_cast<const float2*>(&res[coA + col]);
                const float2 rB = *reinterpret_cast<const float2*>(&res[coB + col]);
                v0.x += rA.x; v0.y += rA.y; v1.x += rB.x; v1.y += rB.y;
            }
            *reinterpret_cast<float2*>(&C[coA + col]) = v0;
            *reinterpret_cast<float2*>(&C[coB + col]) = v1;
            if (SPLIT) {
                bf16 h0 = __float2bfloat16(v0.x), h1 = __float2bfloat16(v0.y);
                bf16 h2 = __float2bfloat16(v1.x), h3 = __float2bfloat16(v1.y);
                *reinterpret_cast<__nv_bfloat162*>(&Ch[coA + col]) = __nv_bfloat162(h0, h1);
                *reinterpret_cast<__nv_bfloat162*>(&Ch[coB + col]) = __nv_bfloat162(h2, h3);
                *reinterpret_cast<__nv_bfloat162*>(&Cl[coA + col]) = __nv_bfloat162(
                    __float2bfloat16(v0.x - __bfloat162float(h0)),
                    __float2bfloat16(v0.y - __bfloat162float(h1)));
                *reinterpret_cast<__nv_bfloat162*>(&Cl[coB + col]) = __nv_bfloat162(
                    __float2bfloat16(v1.x - __bfloat162float(h2)),
                    __float2bfloat16(v1.y - __bfloat162float(h3)));
            }
        }
    }
}

// ================= split / transpose conversions =================
__global__ void split_k(const float* __restrict__ in, bf16* __restrict__ oh,
                        bf16* __restrict__ ol, size_t n4)
{
    size_t i = (size_t)blockIdx.x * blockDim.x + threadIdx.x;
    if (i >= n4) return;
    float4 v = reinterpret_cast<const float4*>(in)[i];
    bf16 h0 = __float2bfloat16(v.x), h1 = __float2bfloat16(v.y);
    bf16 h2 = __float2bfloat16(v.z), h3 = __float2bfloat16(v.w);
    __nv_bfloat162 hA(h0, h1), hB(h2, h3);
    __nv_bfloat162 lA(__float2bfloat16(v.x - __bfloat162float(h0)),
                      __float2bfloat16(v.y - __bfloat162float(h1)));
    __nv_bfloat162 lB(__float2bfloat16(v.z - __bfloat162float(h2)),
                      __float2bfloat16(v.w - __bfloat162float(h3)));
    reinterpret_cast<__nv_bfloat162*>(oh)[2 * i]     = hA;
    reinterpret_cast<__nv_bfloat162*>(oh)[2 * i + 1] = hB;
    reinterpret_cast<__nv_bfloat162*>(ol)[2 * i]     = lA;
    reinterpret_cast<__nv_bfloat162*>(ol)[2 * i + 1] = lB;
}

// in [Z][R,C] fp32 -> out [Z][C,R] bf16 hi/lo
__global__ void splitT_k(const float* __restrict__ in, bf16* __restrict__ oh,
                         bf16* __restrict__ ol, int R, int C)
{
    __shared__ float t[32][33];
    const size_t zo = (size_t)blockIdx.z * R * C;
    const int c0 = blockIdx.x * 32, r0 = blockIdx.y * 32;
    const int lx = threadIdx.x & 31, ly = threadIdx.x >> 5;
#pragma unroll
    for (int i = 0; i < 4; i++)
        t[ly + 8 * i][lx] = in[zo + (size_t)(r0 + ly + 8 * i) * C + c0 + lx];
    __syncthreads();
#pragma unroll
    for (int i = 0; i < 4; i++) {
        const int c = ly + 8 * i;
        const float v = t[lx][c];
        const size_t o = zo + (size_t)(c0 + c) * R + r0 + lx;
        bf16 h = __float2bfloat16(v);
        oh[o] = h;
        ol[o] = __float2bfloat16(v - __bfloat162float(h));
    }
}

// ================= softmaxes / LN =================
__global__ void dispatch_softmax_k(const float* __restrict__ w, float* __restrict__ out)
{
    const int b = blockIdx.y, lane = threadIdx.x & 31, grp = threadIdx.x >> 5;
    const int col = blockIdx.x * 32 + lane;
    const float* p = w   + (size_t)b * Nq * ESq + col;
    float*       o = out + (size_t)b * Nq * ESq + col;
    __shared__ float red[8][33];

    float mx = -1e30f;
    for (int n = grp; n < Nq; n += 8) mx = fmaxf(mx, p[(size_t)n * ESq]);
    red[grp][lane] = mx;
    __syncthreads();
    if (grp == 0) {
        float m = red[0][lane];
#pragma unroll
        for (int g = 1; g < 8; g++) m = fmaxf(m, red[g][lane]);
        red[0][lane] = m;
    }
    __syncthreads();
    const float m = red[0][lane];
    __syncthreads();

    float s = 0.f;
    for (int n = grp; n < Nq; n += 8) s += __expf(p[(size_t)n * ESq] - m);
    red[grp][lane] = s;
    __syncthreads();
    if (grp == 0) {
        float t2 = red[0][lane];
#pragma unroll
        for (int g = 1; g < 8; g++) t2 += red[g][lane];
        red[0][lane] = t2;
    }
    __syncthreads();
    const float inv = 1.f / red[0][lane];
    for (int n = grp; n < Nq; n += 8)
        o[(size_t)n * ESq] = __expf(p[(size_t)n * ESq] - m) * inv;
}

__global__ void row_softmax_split_k(const float* __restrict__ w,
                                    bf16* __restrict__ oh, bf16* __restrict__ ol)
{
    const size_t r = blockIdx.x;
    const float* p = w + r * ESq;
    const int tid = threadIdx.x;
    __shared__ float buf[256];

    float v[4];
    float mx = -1e30f;
#pragma unroll
    for (int j = 0; j < 4; j++) { v[j] = p[tid + 256 * j]; mx = fmaxf(mx, v[j]); }
    buf[tid] = mx;
    __syncthreads();
    for (int off = 128; off > 0; off >>= 1) {
        if (tid < off) buf[tid] = fmaxf(buf[tid], buf[tid + off]);
        __syncthreads();
    }
    const float m = buf[0];
    __syncthreads();
    float s = 0.f;
#pragma unroll
    for (int j = 0; j < 4; j++) { v[j] = __expf(v[j] - m); s += v[j]; }
    buf[tid] = s;
    __syncthreads();
    for (int off = 128; off > 0; off >>= 1) {
        if (tid < off) buf[tid] += buf[tid + off];
        __syncthreads();
    }
    const float inv = 1.f / buf[0];
#pragma unroll
    for (int j = 0; j < 4; j++) {
        const float val = v[j] * inv;
        bf16 h = __float2bfloat16(val);
        oh[r * ESq + tid + 256 * j] = h;
        ol[r * ESq + tid + 256 * j] = __float2bfloat16(val - __bfloat162float(h));
    }
}

__global__ void ln_relu_k(const float* __restrict__ h, const float* __restrict__ xin,
                          const float* __restrict__ g, const float* __restrict__ be,
                          float* __restrict__ x2, bf16* __restrict__ oh, bf16* __restrict__ ol)
{
    const int r = blockIdx.x;
    const int e = (r / Sq) % Eq;
    const float* hr = h   + (size_t)r * Dq;
    const float* xr = xin + (size_t)r * Dq;
    const int tid = threadIdx.x;
    __shared__ float rs[256], rs2[256];

    float v[4];
    float s = 0.f, s2 = 0.f;
#pragma unroll
    for (int j = 0; j < 4; j++) {
        v[j] = hr[tid + 256 * j];
        s += v[j]; s2 += v[j] * v[j];
    }
    rs[tid] = s; rs2[tid] = s2;
    __syncthreads();
    for (int off = 128; off > 0; off >>= 1) {
        if (tid < off) { rs[tid] += rs[tid + off]; rs2[tid] += rs2[tid + off]; }
        __syncthreads();
    }
    const float mean = rs[0] * (1.f / Dq);
    const float var  = rs2[0] * (1.f / Dq) - mean * mean;
    const float rstd = rsqrtf(var + EPSq);

#pragma unroll
    for (int j = 0; j < 4; j++) {
        const int d = tid + 256 * j;
        const float ln = (v[j] - mean) * rstd * g[(size_t)e * Dq + d] + be[(size_t)e * Dq + d];
        const float val = xr[d] + fmaxf(ln, 0.f);
        const size_t o = (size_t)r * Dq + d;
        x2[o] = val;
        bf16 hh = __float2bfloat16(val);
        oh[o] = hh;
        ol[o] = __float2bfloat16(val - __bfloat162float(hh));
    }
}

// ================= launch =================
extern "C" void kernel_launch(void* const* d_in, const int* in_sizes, int n_in,
                              void* d_out, int out_size)
{
    const float* x   = (const float*)d_in[0];
    const float* phi = (const float*)d_in[1];
    const float* W1  = (const float*)d_in[2];
    const float* b1  = (const float*)d_in[3];
    const float* g1  = (const float*)d_in[4];
    const float* be1 = (const float*)d_in[5];
    const float* W2  = (const float*)d_in[6];
    const float* b2  = (const float*)d_in[7];
    float* out = (float*)d_out;

    cudaFuncSetAttribute(mma_gemm_k<0,0>, cudaFuncAttributeMaxDynamicSharedMemorySize, SMEM_DYN);
    cudaFuncSetAttribute(mma_gemm_k<0,1>, cudaFuncAttributeMaxDynamicSharedMemorySize, SMEM_DYN);
    cudaFuncSetAttribute(mma_gemm_k<1,0>, cudaFuncAttributeMaxDynamicSharedMemorySize, SMEM_DYN);
    cudaFuncSetAttribute(mma_gemm_k<2,0>, cudaFuncAttributeMaxDynamicSharedMemorySize, SMEM_DYN);

    float *w, *dsp, *xin, *h, *x2, *y;
    cudaGetSymbolAddress((void**)&w,   g_w);
    cudaGetSymbolAddress((void**)&dsp, g_dsp);
    cudaGetSymbolAddress((void**)&xin, g_xin);
    cudaGetSymbolAddress((void**)&h,   g_h);
    cudaGetSymbolAddress((void**)&x2,  g_x2);
    cudaGetSymbolAddress((void**)&y,   g_y);

    bf16 *xs_h,*xs_l,*xT_h,*xT_l,*phiT_h,*phiT_l,*W1T_h,*W1T_l,*W2T_h,*W2T_l;
    bf16 *dspT_h,*dspT_l,*xinS_h,*xinS_l,*x2S_h,*x2S_l,*yT_h,*yT_l,*cmb_h,*cmb_l;
    cudaGetSymbolAddress((void**)&xs_h, g_xs_h);   cudaGetSymbolAddress((void**)&xs_l, g_xs_l);
    cudaGetSymbolAddress((void**)&xT_h, g_xT_h);   cudaGetSymbolAddress((void**)&xT_l, g_xT_l);
    cudaGetSymbolAddress((void**)&phiT_h, g_phiT_h); cudaGetSymbolAddress((void**)&phiT_l, g_phiT_l);
    cudaGetSymbolAddress((void**)&W1T_h, g_W1T_h); cudaGetSymbolAddress((void**)&W1T_l, g_W1T_l);
    cudaGetSymbolAddress((void**)&W2T_h, g_W2T_h); cudaGetSymbolAddress((void**)&W2T_l, g_W2T_l);
    cudaGetSymbolAddress((void**)&dspT_h, g_dspT_h); cudaGetSymbolAddress((void**)&dspT_l, g_dspT_l);
    cudaGetSymbolAddress((void**)&xinS_h, g_xinS_h); cudaGetSymbolAddress((void**)&xinS_l, g_xinS_l);
    cudaGetSymbolAddress((void**)&x2S_h, g_x2S_h); cudaGetSymbolAddress((void**)&x2S_l, g_x2S_l);
    cudaGetSymbolAddress((void**)&yT_h, g_yT_h);   cudaGetSymbolAddress((void**)&yT_l, g_yT_l);
    cudaGetSymbolAddress((void**)&cmb_h, g_cmb_h); cudaGetSymbolAddress((void**)&cmb_l, g_cmb_l);

    const size_t EXP = (size_t)Eq * Sq * Dq;

    // conversions
    split_k<<<(Bq*Nq*Dq/4 + 255)/256, 256>>>(x, xs_h, xs_l, (size_t)Bq*Nq*Dq/4);
    splitT_k<<<dim3(Dq/32, Nq/32, Bq), 256>>>(x, xT_h, xT_l, Nq, Dq);
    splitT_k<<<dim3(ESq/32, Dq/32, 1), 256>>>(phi, phiT_h, phiT_l, Dq, ESq);
    splitT_k<<<dim3(Dq/32, Dq/32, Eq), 256>>>(W1, W1T_h, W1T_l, Dq, Dq);
    splitT_k<<<dim3(Dq/32, Dq/32, Eq), 256>>>(W2, W2T_h, W2T_l, Dq, Dq);

    // K1: w[b] = x[b] @ phi    M=2048 N=1024 K=1024
    mma_gemm_k<0,0><<<dim3(ESq/BN, Nq/BM, Bq), 256, SMEM_DYN>>>(
        xs_h, xs_l, phiT_h, phiT_l, nullptr, nullptr, w, nullptr, nullptr,
        Dq, Dq, Dq, ESq,
        (size_t)Nq*Dq, 0, (size_t)Nq*ESq, 1, 0,
        (size_t)64*Dq, (size_t)64*ESq);

    // dispatch softmax (fp32) then transpose-split
    dispatch_softmax_k<<<dim3(ESq/32, Bq), 256>>>(w, dsp);
    splitT_k<<<dim3(ESq/32, Nq/32, Bq), 256>>>(dsp, dspT_h, dspT_l, Nq, ESq);

    // K3: xin[b] = dsp[b]^T @ x[b]   M=1024 N=1024 K=2048  (+ split out)
    mma_gemm_k<0,1><<<dim3(Dq/BN, ESq/BM, Bq), 256, SMEM_DYN>>>(
        dspT_h, dspT_l, xT_h, xT_l, nullptr, nullptr, xin, xinS_h, xinS_l,
        Nq, Nq, Nq, Dq,
        (size_t)ESq*Nq, (size_t)Dq*Nq, (size_t)ESq*Dq, Bq, 0,
        (size_t)64*Nq, (size_t)64*Dq);

    // K4: h[e] = xin_e @ W1[e] + b1[e]   M=512 N=1024 K=1024, z=e
    mma_gemm_k<1,0><<<dim3(Dq/BN, (Bq*Sq)/BM, Eq), 256, SMEM_DYN>>>(
        xinS_h, xinS_l, W1T_h, W1T_l, b1, nullptr, h, nullptr, nullptr,
        Dq, Dq, Dq, Dq,
        (size_t)Sq*Dq, (size_t)Dq*Dq, (size_t)Sq*Dq, Eq, (size_t)Dq,
        EXP, EXP);

    // LN + relu + residual (fp32 + split)
    ln_relu_k<<<Bq*Eq*Sq, 256>>>(h, xin, g1, be1, x2, x2S_h, x2S_l);

    // K6: y[e] = x2 + x2_e @ W2[e] + b2[e]
    mma_gemm_k<2,0><<<dim3(Dq/BN, (Bq*Sq)/BM, Eq), 256, SMEM_DYN>>>(
        x2S_h, x2S_l, W2T_h, W2T_l, b2, x2, y, nullptr, nullptr,
        Dq, Dq, Dq, Dq,
        (size_t)Sq*Dq, (size_t)Dq*Dq, (size_t)Sq*Dq, Eq, (size_t)Dq,
        EXP, EXP);

    // transpose-split y for K8's B operand
    splitT_k<<<dim3(Dq/32, ESq/32, Bq), 256>>>(y, yT_h, yT_l, ESq, Dq);

    // combine softmax -> split bf16
    row_softmax_split_k<<<Bq*Nq, 256>>>(w, cmb_h, cmb_l);

    // K8: out[b] = cmb[b] @ y[b]   M=2048 N=1024 K=1024
    mma_gemm_k<0,0><<<dim3(Dq/BN, Nq/BM, Bq), 256, SMEM_DYN>>>(
        cmb_h, cmb_l, yT_h, yT_l, nullptr, nullptr, out, nullptr, nullptr,
        ESq, ESq, ESq, Dq,
        (size_t)Nq*ESq, (size_t)Dq*ESq, (size_t)Nq*Dq, Bq, 0,
        (size_t)64*ESq, (size_t)64*Dq);
}

// round 5
// speedup vs baseline: 4.3562x; 1.3282x over previous
#include <cuda_runtime.h>
#include <cuda_fp16.h>
#include <math.h>
#include <stdint.h>

typedef __half fp16;

#define Bq   8
#define Nq   2048
#define Dq   1024
#define Eq   16
#define Sq   64
#define ESq  1024
#define EPSq 1e-5f

// ---------------- fp32 scratch ----------------
__device__ __align__(16) float g_w  [(size_t)Bq * Nq * ESq];
__device__ __align__(16) float g_dsp[(size_t)Bq * Nq * ESq];
__device__ __align__(16) float g_xin[(size_t)Bq * Eq * Sq * Dq];
__device__ __align__(16) float g_h  [(size_t)Bq * Eq * Sq * Dq];
__device__ __align__(16) float g_x2 [(size_t)Bq * Eq * Sq * Dq];
__device__ __align__(16) float g_y  [(size_t)Bq * Eq * Sq * Dq];

// ---------------- fp16 split scratch ----------------
__device__ __align__(16) fp16 g_xs_h [(size_t)Bq * Nq * Dq],  g_xs_l [(size_t)Bq * Nq * Dq];
__device__ __align__(16) fp16 g_xT_h [(size_t)Bq * Dq * Nq];
__device__ __align__(16) fp16 g_phiT_h[(size_t)ESq * Dq];
__device__ __align__(16) fp16 g_W1T_h[(size_t)Eq * Dq * Dq];
__device__ __align__(16) fp16 g_W2T_h[(size_t)Eq * Dq * Dq];
__device__ __align__(16) fp16 g_dspT_h[(size_t)Bq * ESq * Nq], g_dspT_l[(size_t)Bq * ESq * Nq];
__device__ __align__(16) fp16 g_xinS_h[(size_t)Bq * Eq * Sq * Dq], g_xinS_l[(size_t)Bq * Eq * Sq * Dq];
__device__ __align__(16) fp16 g_x2S_h[(size_t)Bq * Eq * Sq * Dq],  g_x2S_l[(size_t)Bq * Eq * Sq * Dq];
__device__ __align__(16) fp16 g_yT_h [(size_t)Bq * Dq * ESq];
__device__ __align__(16) fp16 g_cmb_h[(size_t)Bq * Nq * ESq],  g_cmb_l[(size_t)Bq * Nq * ESq];

// ================= mma.sync GEMM =================
#define BM 128
#define BN 128
#define BK 32
#define NSTG 4
#define OFF_AH 0
#define OFF_AL 10240
#define OFF_BH 20480
#define STAGE  30720
#define SMEM_DYN (NSTG * STAGE)

__device__ __forceinline__ uint32_t s2u(const void* p) {
    uint32_t a;
    asm("{ .reg .u64 t; cvta.to.shared.u64 t, %1; cvt.u32.u64 %0, t; }" : "=r"(a) : "l"(p));
    return a;
}
__device__ __forceinline__ void cpa16(uint32_t dst, const void* src) {
    asm volatile("cp.async.cg.shared.global [%0], [%1], 16;" :: "r"(dst), "l"(src));
}
__device__ __forceinline__ void ldm_x4(uint32_t* r, uint32_t a) {
    asm volatile("ldmatrix.sync.aligned.m8n8.x4.shared.b16 {%0,%1,%2,%3}, [%4];"
                 : "=r"(r[0]), "=r"(r[1]), "=r"(r[2]), "=r"(r[3]) : "r"(a));
}
__device__ __forceinline__ void ldm_x2(uint32_t* r, uint32_t a) {
    asm volatile("ldmatrix.sync.aligned.m8n8.x2.shared.b16 {%0,%1}, [%2];"
                 : "=r"(r[0]), "=r"(r[1]) : "r"(a));
}
__device__ __forceinline__ void mma16816(float* c, const uint32_t* a, const uint32_t* b) {
    asm volatile(
        "mma.sync.aligned.m16n8k16.row.col.f32.f16.f16.f32 "
        "{%0,%1,%2,%3}, {%4,%5,%6,%7}, {%8,%9}, {%0,%1,%2,%3};"
        : "+f"(c[0]), "+f"(c[1]), "+f"(c[2]), "+f"(c[3])
        : "r"(a[0]), "r"(a[1]), "r"(a[2]), "r"(a[3]), "r"(b[0]), "r"(b[1]));
}

// C[z] = (Ah+Al)[z] @ Bh[z%bMod]^T (+bias) (+res); fp16 operands, K-major.
// A rows: off = (r>>6)*aRowBlk + (r&63)*lda; C rows likewise via cRowBlk.
// EPI: 0 none, 1 +bias[col], 2 +bias[col]+res. SPLIT: also emit fp16 hi/lo of C.
template<int EPI, int SPLIT>
__global__ void __launch_bounds__(256, 1)
mma_gemm_k(const fp16* __restrict__ Ahb, const fp16* __restrict__ Alb,
           const fp16* __restrict__ Bhb,
           const float* __restrict__ biasb, const float* __restrict__ resb,
           float* __restrict__ Cb, fp16* __restrict__ Chb, fp16* __restrict__ Clb,
           int K, int lda, int ldb, int ldc,
           size_t sA, size_t sB, size_t sC, int bMod, size_t sBias,
           size_t aRowBlk, size_t cRowBlk)
{
    extern __shared__ char sm[];
    const uint32_t sb = s2u(sm);
    const int tid = threadIdx.x, wid = tid >> 5, lane = tid & 31;
    const int z = blockIdx.z;

    const fp16* Ah = Ahb + (size_t)z * sA;
    const fp16* Al = Alb + (size_t)z * sA;
    const fp16* Bh = Bhb + (size_t)(z % bMod) * sB;

    const int m0 = blockIdx.y * BM;
    const int n0 = blockIdx.x * BN;

    // per-thread cp.async maps: 512 16B-chunks per operand, 2 per thread
    size_t aoff[2], boff[2];
    uint32_t dst[2];
#pragma unroll
    for (int i = 0; i < 2; i++) {
        const int idx = tid + i * 256;
        const int row = idx >> 2, kc = idx & 3;
        const int m = m0 + row;
        aoff[i] = ((size_t)(m >> 6)) * aRowBlk + (size_t)(m & 63) * lda + kc * 8;
        boff[i] = (size_t)(n0 + row) * ldb + kc * 8;
        dst[i]  = (uint32_t)(row * 80 + kc * 16);
    }

    auto load_stage = [&](int t) {
        const uint32_t stg = sb + (t % NSTG) * STAGE;
        const size_t ke = (size_t)t * BK;
#pragma unroll
        for (int i = 0; i < 2; i++) {
            cpa16(stg + OFF_AH + dst[i], Ah + aoff[i] + ke);
            cpa16(stg + OFF_AL + dst[i], Al + aoff[i] + ke);
            cpa16(stg + OFF_BH + dst[i], Bh + boff[i] + ke);
        }
        asm volatile("cp.async.commit_group;" ::: "memory");
    };

    const int wm = (wid >> 2) * 64;
    const int wn = (wid & 3) * 32;

    float acc[4][4][4];
#pragma unroll
    for (int mi = 0; mi < 4; mi++)
#pragma unroll
        for (int ni = 0; ni < 4; ni++)
#pragma unroll
            for (int q = 0; q < 4; q++) acc[mi][ni][q] = 0.f;

    const int nt = K / BK;
#pragma unroll
    for (int t = 0; t < NSTG - 1; t++)
        if (t < nt) load_stage(t);

    for (int t = 0; t < nt; t++) {
        const int rem = nt - 1 - t;   // commits issued after stage t
        if (rem >= 2)      asm volatile("cp.async.wait_group 2;" ::: "memory");
        else if (rem == 1) asm volatile("cp.async.wait_group 1;" ::: "memory");
        else               asm volatile("cp.async.wait_group 0;" ::: "memory");
        __syncthreads();

        if (t + NSTG - 1 < nt) load_stage(t + NSTG - 1);

        const uint32_t stg = sb + (t % NSTG) * STAGE;
#pragma unroll
        for (int ks = 0; ks < 2; ks++) {
            const int kb = ks * 16;
            uint32_t ah[4][4], al[4][4], bh[4][2];
#pragma unroll
            for (int mi = 0; mi < 4; mi++) {
                const uint32_t ao =
                    (uint32_t)((wm + mi * 16 + (lane & 15)) * 80 + (kb + (lane >> 4) * 8) * 2);
                ldm_x4(ah[mi], stg + OFF_AH + ao);
                ldm_x4(al[mi], stg + OFF_AL + ao);
            }
#pragma unroll
            for (int ni = 0; ni < 4; ni++) {
                const uint32_t bo =
                    (uint32_t)((wn + ni * 8 + (lane & 7)) * 80 + (kb + ((lane >> 3) & 1) * 8) * 2);
                ldm_x2(bh[ni], stg + OFF_BH + bo);
            }
#pragma unroll
            for (int mi = 0; mi < 4; mi++)
#pragma unroll
                for (int ni = 0; ni < 4; ni++) {
                    mma16816(acc[mi][ni], ah[mi], bh[ni]);
                    mma16816(acc[mi][ni], al[mi], bh[ni]);
                }
        }
    }

    // ---------------- epilogue (direct stores) ----------------
    float*       C  = Cb + (size_t)z * sC;
    fp16*        Ch = SPLIT ? (Chb + (size_t)z * sC) : nullptr;
    fp16*        Cl = SPLIT ? (Clb + (size_t)z * sC) : nullptr;
    const float* bias = (EPI >= 1) ? (biasb + (size_t)(z % bMod) * sBias) : nullptr;
    const float* res  = (EPI == 2) ? (resb  + (size_t)z * sC) : nullptr;

#pragma unroll
    for (int mi = 0; mi < 4; mi++) {
        const int mA = m0 + wm + mi * 16 + (lane >> 2);
        const int mB = mA + 8;
        const size_t coA = ((size_t)(mA >> 6)) * cRowBlk + (size_t)(mA & 63) * ldc;
        const size_t coB = ((size_t)(mB >> 6)) * cRowBlk + (size_t)(mB & 63) * ldc;
#pragma unroll
        for (int ni = 0; ni < 4; ni++) {
            const int col = n0 + wn + ni * 8 + (lane & 3) * 2;
            float2 v0 = make_float2(acc[mi][ni][0], acc[mi][ni][1]);
            float2 v1 = make_float2(acc[mi][ni][2], acc[mi][ni][3]);
            if (EPI >= 1) {
                const float2 bb = *reinterpret_cast<const float2*>(&bias[col]);
                v0.x += bb.x; v0.y += bb.y; v1.x += bb.x; v1.y += bb.y;
            }
            if (EPI == 2) {
                const float2 rA = *reinterpret_cast<const float2*>(&res[coA + col]);
                const float2 rB = *reinterpret_cast<const float2*>(&res[coB + col]);
                v0.x += rA.x; v0.y += rA.y; v1.x += rB.x; v1.y += rB.y;
            }
            *reinterpret_cast<float2*>(&C[coA + col]) = v0;
            *reinterpret_cast<float2*>(&C[coB + col]) = v1;
            if (SPLIT) {
                fp16 h0 = __float2half_rn(v0.x), h1 = __float2half_rn(v0.y);
                fp16 h2 = __float2half_rn(v1.x), h3 = __float2half_rn(v1.y);
                *reinterpret_cast<__half2*>(&Ch[coA + col]) = __halves2half2(h0, h1);
                *reinterpret_cast<__half2*>(&Ch[coB + col]) = __halves2half2(h2, h3);
                *reinterpret_cast<__half2*>(&Cl[coA + col]) = __halves2half2(
                    __float2half_rn(v0.x - __half2float(h0)),
                    __float2half_rn(v0.y - __half2float(h1)));
                *reinterpret_cast<__half2*>(&Cl[coB + col]) = __halves2half2(
                    __float2half_rn(v1.x - __half2float(h2)),
                    __float2half_rn(v1.y - __half2float(h3)));
            }
        }
    }
}

// ================= split / transpose conversions =================
__global__ void split_k(const float* __restrict__ in, fp16* __restrict__ oh,
                        fp16* __restrict__ ol, size_t n4)
{
    size_t i = (size_t)blockIdx.x * blockDim.x + threadIdx.x;
    if (i >= n4) return;
    float4 v = reinterpret_cast<const float4*>(in)[i];
    fp16 h0 = __float2half_rn(v.x), h1 = __float2half_rn(v.y);
    fp16 h2 = __float2half_rn(v.z), h3 = __float2half_rn(v.w);
    reinterpret_cast<__half2*>(oh)[2 * i]     = __halves2half2(h0, h1);
    reinterpret_cast<__half2*>(oh)[2 * i + 1] = __halves2half2(h2, h3);
    reinterpret_cast<__half2*>(ol)[2 * i]     = __halves2half2(
        __float2half_rn(v.x - __half2float(h0)), __float2half_rn(v.y - __half2float(h1)));
    reinterpret_cast<__half2*>(ol)[2 * i + 1] = __halves2half2(
        __float2half_rn(v.z - __half2float(h2)), __float2half_rn(v.w - __half2float(h3)));
}

// in [Z][R,C] fp32 -> out [Z][C,R] fp16 hi (and lo if LO)
template<int LO>
__global__ void splitT_k(const float* __restrict__ in, fp16* __restrict__ oh,
                         fp16* __restrict__ ol, int R, int C)
{
    __shared__ float t[32][33];
    const size_t zo = (size_t)blockIdx.z * R * C;
    const int c0 = blockIdx.x * 32, r0 = blockIdx.y * 32;
    const int lx = threadIdx.x & 31, ly = threadIdx.x >> 5;
#pragma unroll
    for (int i = 0; i < 4; i++)
        t[ly + 8 * i][lx] = in[zo + (size_t)(r0 + ly + 8 * i) * C + c0 + lx];
    __syncthreads();
#pragma unroll
    for (int i = 0; i < 4; i++) {
        const int c = ly + 8 * i;
        const float v = t[lx][c];
        const size_t o = zo + (size_t)(c0 + c) * R + r0 + lx;
        fp16 h = __float2half_rn(v);
        oh[o] = h;
        if (LO) ol[o] = __float2half_rn(v - __half2float(h));
    }
}

// ================= softmaxes / LN =================
__global__ void dispatch_softmax_k(const float* __restrict__ w, float* __restrict__ out)
{
    const int b = blockIdx.y, lane = threadIdx.x & 31, grp = threadIdx.x >> 5;
    const int col = blockIdx.x * 32 + lane;
    const float* p = w   + (size_t)b * Nq * ESq + col;
    float*       o = out + (size_t)b * Nq * ESq + col;
    __shared__ float red[8][33];

    float mx = -1e30f;
    for (int n = grp; n < Nq; n += 8) mx = fmaxf(mx, p[(size_t)n * ESq]);
    red[grp][lane] = mx;
    __syncthreads();
    if (grp == 0) {
        float m = red[0][lane];
#pragma unroll
        for (int g = 1; g < 8; g++) m = fmaxf(m, red[g][lane]);
        red[0][lane] = m;
    }
    __syncthreads();
    const float m = red[0][lane];
    __syncthreads();

    float s = 0.f;
    for (int n = grp; n < Nq; n += 8) s += __expf(p[(size_t)n * ESq] - m);
    red[grp][lane] = s;
    __syncthreads();
    if (grp == 0) {
        float t2 = red[0][lane];
#pragma unroll
        for (int g = 1; g < 8; g++) t2 += red[g][lane];
        red[0][lane] = t2;
    }
    __syncthreads();
    const float inv = 1.f / red[0][lane];
    for (int n = grp; n < Nq; n += 8)
        o[(size_t)n * ESq] = __expf(p[(size_t)n * ESq] - m) * inv;
}

__global__ void row_softmax_split_k(const float* __restrict__ w,
                                    fp16* __restrict__ oh, fp16* __restrict__ ol)
{
    const size_t r = blockIdx.x;
    const float* p = w + r * ESq;
    const int tid = threadIdx.x;
    __shared__ float buf[256];

    float v[4];
    float mx = -1e30f;
#pragma unroll
    for (int j = 0; j < 4; j++) { v[j] = p[tid + 256 * j]; mx = fmaxf(mx, v[j]); }
    buf[tid] = mx;
    __syncthreads();
    for (int off = 128; off > 0; off >>= 1) {
        if (tid < off) buf[tid] = fmaxf(buf[tid], buf[tid + off]);
        __syncthreads();
    }
    const float m = buf[0];
    __syncthreads();
    float s = 0.f;
#pragma unroll
    for (int j = 0; j < 4; j++) { v[j] = __expf(v[j] - m); s += v[j]; }
    buf[tid] = s;
    __syncthreads();
    for (int off = 128; off > 0; off >>= 1) {
        if (tid < off) buf[tid] += buf[tid + off];
        __syncthreads();
    }
    const float inv = 1.f / buf[0];
#pragma unroll
    for (int j = 0; j < 4; j++) {
        const float val = v[j] * inv;
        fp16 h = __float2half_rn(val);
        oh[r * ESq + tid + 256 * j] = h;
        ol[r * ESq + tid + 256 * j] = __float2half_rn(val - __half2float(h));
    }
}

__global__ void ln_relu_k(const float* __restrict__ h, const float* __restrict__ xin,
                          const float* __restrict__ g, const float* __restrict__ be,
                          float* __restrict__ x2, fp16* __restrict__ oh, fp16* __restrict__ ol)
{
    const int r = blockIdx.x;
    const int e = (r / Sq) % Eq;
    const float* hr = h   + (size_t)r * Dq;
    const float* xr = xin + (size_t)r * Dq;
    const int tid = threadIdx.x;
    __shared__ float rs[256], rs2[256];

    float v[4];
    float s = 0.f, s2 = 0.f;
#pragma unroll
    for (int j = 0; j < 4; j++) {
        v[j] = hr[tid + 256 * j];
        s += v[j]; s2 += v[j] * v[j];
    }
    rs[tid] = s; rs2[tid] = s2;
    __syncthreads();
    for (int off = 128; off > 0; off >>= 1) {
        if (tid < off) { rs[tid] += rs[tid + off]; rs2[tid] += rs2[tid + off]; }
        __syncthreads();
    }
    const float mean = rs[0] * (1.f / Dq);
    const float var  = rs2[0] * (1.f / Dq) - mean * mean;
    const float rstd = rsqrtf(var + EPSq);

#pragma unroll
    for (int j = 0; j < 4; j++) {
        const int d = tid + 256 * j;
        const float ln = (v[j] - mean) * rstd * g[(size_t)e * Dq + d] + be[(size_t)e * Dq + d];
        const float val = xr[d] + fmaxf(ln, 0.f);
        const size_t o = (size_t)r * Dq + d;
        x2[o] = val;
        fp16 hh = __float2half_rn(val);
        oh[o] = hh;
        ol[o] = __float2half_rn(val - __half2float(hh));
    }
}

// ================= launch =================
extern "C" void kernel_launch(void* const* d_in, const int* in_sizes, int n_in,
                              void* d_out, int out_size)
{
    const float* x   = (const float*)d_in[0];
    const float* phi = (const float*)d_in[1];
    const float* W1  = (const float*)d_in[2];
    const float* b1  = (const float*)d_in[3];
    const float* g1  = (const float*)d_in[4];
    const float* be1 = (const float*)d_in[5];
    const float* W2  = (const float*)d_in[6];
    const float* b2  = (const float*)d_in[7];
    float* out = (float*)d_out;

    cudaFuncSetAttribute(mma_gemm_k<0,0>, cudaFuncAttributeMaxDynamicSharedMemorySize, SMEM_DYN);
    cudaFuncSetAttribute(mma_gemm_k<0,1>, cudaFuncAttributeMaxDynamicSharedMemorySize, SMEM_DYN);
    cudaFuncSetAttribute(mma_gemm_k<1,0>, cudaFuncAttributeMaxDynamicSharedMemorySize, SMEM_DYN);
    cudaFuncSetAttribute(mma_gemm_k<2,0>, cudaFuncAttributeMaxDynamicSharedMemorySize, SMEM_DYN);

    float *w, *dsp, *xin, *h, *x2, *y;
    cudaGetSymbolAddress((void**)&w,   g_w);
    cudaGetSymbolAddress((void**)&dsp, g_dsp);
    cudaGetSymbolAddress((void**)&xin, g_xin);
    cudaGetSymbolAddress((void**)&h,   g_h);
    cudaGetSymbolAddress((void**)&x2,  g_x2);
    cudaGetSymbolAddress((void**)&y,   g_y);

    fp16 *xs_h,*xs_l,*xT_h,*phiT_h,*W1T_h,*W2T_h;
    fp16 *dspT_h,*dspT_l,*xinS_h,*xinS_l,*x2S_h,*x2S_l,*yT_h,*cmb_h,*cmb_l;
    cudaGetSymbolAddress((void**)&xs_h, g_xs_h);   cudaGetSymbolAddress((void**)&xs_l, g_xs_l);
    cudaGetSymbolAddress((void**)&xT_h, g_xT_h);
    cudaGetSymbolAddress((void**)&phiT_h, g_phiT_h);
    cudaGetSymbolAddress((void**)&W1T_h, g_W1T_h);
    cudaGetSymbolAddress((void**)&W2T_h, g_W2T_h);
    cudaGetSymbolAddress((void**)&dspT_h, g_dspT_h); cudaGetSymbolAddress((void**)&dspT_l, g_dspT_l);
    cudaGetSymbolAddress((void**)&xinS_h, g_xinS_h); cudaGetSymbolAddress((void**)&xinS_l, g_xinS_l);
    cudaGetSymbolAddress((void**)&x2S_h, g_x2S_h); cudaGetSymbolAddress((void**)&x2S_l, g_x2S_l);
    cudaGetSymbolAddress((void**)&yT_h, g_yT_h);
    cudaGetSymbolAddress((void**)&cmb_h, g_cmb_h); cudaGetSymbolAddress((void**)&cmb_l, g_cmb_l);

    const size_t EXP = (size_t)Eq * Sq * Dq;

    // conversions
    split_k<<<(Bq*Nq*Dq/4 + 255)/256, 256>>>(x, xs_h, xs_l, (size_t)Bq*Nq*Dq/4);
    splitT_k<0><<<dim3(Dq/32, Nq/32, Bq), 256>>>(x, xT_h, nullptr, Nq, Dq);
    splitT_k<0><<<dim3(ESq/32, Dq/32, 1), 256>>>(phi, phiT_h, nullptr, Dq, ESq);
    splitT_k<0><<<dim3(Dq/32, Dq/32, Eq), 256>>>(W1, W1T_h, nullptr, Dq, Dq);
    splitT_k<0><<<dim3(Dq/32, Dq/32, Eq), 256>>>(W2, W2T_h, nullptr, Dq, Dq);

    // K1: w[b] = x[b] @ phi    M=2048 N=1024 K=1024
    mma_gemm_k<0,0><<<dim3(ESq/BN, Nq/BM, Bq), 256, SMEM_DYN>>>(
        xs_h, xs_l, phiT_h, nullptr, nullptr, w, nullptr, nullptr,
        Dq, Dq, Dq, ESq,
        (size_t)Nq*Dq, 0, (size_t)Nq*ESq, 1, 0,
        (size_t)64*Dq, (size_t)64*ESq);

    // dispatch softmax (fp32) then transpose-split (hi+lo: it is the A operand of K3)
    dispatch_softmax_k<<<dim3(ESq/32, Bq), 256>>>(w, dsp);
    splitT_k<1><<<dim3(ESq/32, Nq/32, Bq), 256>>>(dsp, dspT_h, dspT_l, Nq, ESq);

    // K3: xin[b] = dsp[b]^T @ x[b]   M=1024 N=1024 K=2048  (+ split out)
    mma_gemm_k<0,1><<<dim3(Dq/BN, ESq/BM, Bq), 256, SMEM_DYN>>>(
        dspT_h, dspT_l, xT_h, nullptr, nullptr, xin, xinS_h, xinS_l,
        Nq, Nq, Nq, Dq,
        (size_t)ESq*Nq, (size_t)Dq*Nq, (size_t)ESq*Dq, Bq, 0,
        (size_t)64*Nq, (size_t)64*Dq);

    // K4: h[e] = xin_e @ W1[e] + b1[e]   M=512 N=1024 K=1024, z=e
    mma_gemm_k<1,0><<<dim3(Dq/BN, (Bq*Sq)/BM, Eq), 256, SMEM_DYN>>>(
        xinS_h, xinS_l, W1T_h, b1, nullptr, h, nullptr, nullptr,
        Dq, Dq, Dq, Dq,
        (size_t)Sq*Dq, (size_t)Dq*Dq, (size_t)Sq*Dq, Eq, (size_t)Dq,
        EXP, EXP);

    // LN + relu + residual (fp32 + split)
    ln_relu_k<<<Bq*Eq*Sq, 256>>>(h, xin, g1, be1, x2, x2S_h, x2S_l);

    // K6: y[e] = x2 + x2_e @ W2[e] + b2[e]
    mma_gemm_k<2,0><<<dim3(Dq/BN, (Bq*Sq)/BM, Eq), 256, SMEM_DYN>>>(
        x2S_h, x2S_l, W2T_h, b2, x2, y, nullptr, nullptr,
        Dq, Dq, Dq, Dq,
        (size_t)Sq*Dq, (size_t)Dq*Dq, (size_t)Sq*Dq, Eq, (size_t)Dq,
        EXP, EXP);

    // transpose y for K8's B operand (hi only)
    splitT_k<0><<<dim3(Dq/32, ESq/32, Bq), 256>>>(y, yT_h, nullptr, ESq, Dq);

    // combine softmax -> split fp16 (A operand of K8: hi+lo)
    row_softmax_split_k<<<Bq*Nq, 256>>>(w, cmb_h, cmb_l);

    // K8: out[b] = cmb[b] @ y[b]   M=2048 N=1024 K=1024
    mma_gemm_k<0,0><<<dim3(Dq/BN, Nq/BM, Bq), 256, SMEM_DYN>>>(
        cmb_h, cmb_l, yT_h, nullptr, nullptr, out, nullptr, nullptr,
        ESq, ESq, ESq, Dq,
        (size_t)Nq*ESq, (size_t)Dq*ESq, (size_t)Nq*Dq, Bq, 0,
        (size_t)64*ESq, (size_t)64*Dq);
}

// round 6
// speedup vs baseline: 4.8685x; 1.1176x over previous
#include <cuda_runtime.h>
#include <cuda_fp16.h>
#include <math.h>
#include <stdint.h>

typedef __half fp16;

#define Bq   8
#define Nq   2048
#define Dq   1024
#define Eq   16
#define Sq   64
#define ESq  1024
#define EPSq 1e-5f

// ---------------- fp32 scratch ----------------
__device__ __align__(16) float g_w  [(size_t)Bq * Nq * ESq];
__device__ __align__(16) float g_h  [(size_t)Bq * Eq * Sq * Dq];
__device__ __align__(16) float g_y  [(size_t)Bq * Eq * Sq * Dq];

// ---------------- fp16 split scratch ----------------
__device__ __align__(16) fp16 g_xs_h [(size_t)Bq * Nq * Dq],  g_xs_l [(size_t)Bq * Nq * Dq];
__device__ __align__(16) fp16 g_xT_h [(size_t)Bq * Dq * Nq];
__device__ __align__(16) fp16 g_phiT_h[(size_t)ESq * Dq];
__device__ __align__(16) fp16 g_W1T_h[(size_t)Eq * Dq * Dq];
__device__ __align__(16) fp16 g_W2T_h[(size_t)Eq * Dq * Dq];
__device__ __align__(16) fp16 g_dspT_h[(size_t)Bq * ESq * Nq], g_dspT_l[(size_t)Bq * ESq * Nq];
__device__ __align__(16) fp16 g_xinS_h[(size_t)Bq * Eq * Sq * Dq], g_xinS_l[(size_t)Bq * Eq * Sq * Dq];
__device__ __align__(16) fp16 g_x2S_h[(size_t)Bq * Eq * Sq * Dq],  g_x2S_l[(size_t)Bq * Eq * Sq * Dq];
__device__ __align__(16) fp16 g_yT_h [(size_t)Bq * Dq * ESq];
__device__ __align__(16) fp16 g_cmb_h[(size_t)Bq * Nq * ESq],  g_cmb_l[(size_t)Bq * Nq * ESq];

// ================= mma.sync GEMM =================
#define BM 128
#define BN 128
#define BK 64
#define NSTG 3
#define PITCH 144                    // 64 fp16 = 128B + 16B pad
#define HALF_BYTES (128 * PITCH)     // 18432
#define OFF_AH 0
#define OFF_AL HALF_BYTES
#define OFF_BH (2 * HALF_BYTES)
#define STAGE  (3 * HALF_BYTES)      // 55296
#define SMEM_DYN (NSTG * STAGE)      // 165888

__device__ __forceinline__ uint32_t s2u(const void* p) {
    uint32_t a;
    asm("{ .reg .u64 t; cvta.to.shared.u64 t, %1; cvt.u32.u64 %0, t; }" : "=r"(a) : "l"(p));
    return a;
}
__device__ __forceinline__ void cpa16(uint32_t dst, const void* src) {
    asm volatile("cp.async.cg.shared.global [%0], [%1], 16;" :: "r"(dst), "l"(src));
}
__device__ __forceinline__ void ldm_x4(uint32_t* r, uint32_t a) {
    asm volatile("ldmatrix.sync.aligned.m8n8.x4.shared.b16 {%0,%1,%2,%3}, [%4];"
                 : "=r"(r[0]), "=r"(r[1]), "=r"(r[2]), "=r"(r[3]) : "r"(a));
}
__device__ __forceinline__ void mma16816(float* c, const uint32_t* a, const uint32_t* b) {
    asm volatile(
        "mma.sync.aligned.m16n8k16.row.col.f32.f16.f16.f32 "
        "{%0,%1,%2,%3}, {%4,%5,%6,%7}, {%8,%9}, {%0,%1,%2,%3};"
        : "+f"(c[0]), "+f"(c[1]), "+f"(c[2]), "+f"(c[3])
        : "r"(a[0]), "r"(a[1]), "r"(a[2]), "r"(a[3]), "r"(b[0]), "r"(b[1]));
}

// C[z] = (Ah+Al)[z] @ Bh[z%bMod]^T.  A rows: (r>>6)*aRowBlk + (r&63)*lda; C likewise.
// EPI: 0 none, 1 +bias[col], 3 +bias[col] + (resh+resl)[row,col]
// WC: write fp32 C.  SPLIT: write fp16 hi/lo of result.
template<int EPI, int WC, int SPLIT>
__global__ void __launch_bounds__(256, 1)
mma_gemm_k(const fp16* __restrict__ Ahb, const fp16* __restrict__ Alb,
           const fp16* __restrict__ Bhb,
           const float* __restrict__ biasb,
           const fp16* __restrict__ reshb, const fp16* __restrict__ reslb,
           float* __restrict__ Cb, fp16* __restrict__ Chb, fp16* __restrict__ Clb,
           int K, int lda, int ldb, int ldc,
           size_t sA, size_t sB, size_t sC, int bMod, size_t sBias,
           size_t aRowBlk, size_t cRowBlk)
{
    extern __shared__ char sm[];
    const uint32_t sb = s2u(sm);
    const int tid = threadIdx.x, wid = tid >> 5, lane = tid & 31;
    const int z = blockIdx.z;

    const fp16* Ah = Ahb + (size_t)z * sA;
    const fp16* Al = Alb + (size_t)z * sA;
    const fp16* Bh = Bhb + (size_t)(z % bMod) * sB;

    const int m0 = blockIdx.y * BM;
    const int n0 = blockIdx.x * BN;

    // cp.async maps: 128 rows x 8 chunks(16B) per operand-half; 4 chunks/thread
    size_t aoff[4], boff[4];
    uint32_t dst[4];
#pragma unroll
    for (int i = 0; i < 4; i++) {
        const int idx = tid + i * 256;
        const int row = idx >> 3, kc = idx & 7;
        const int m = m0 + row;
        aoff[i] = ((size_t)(m >> 6)) * aRowBlk + (size_t)(m & 63) * lda + kc * 8;
        boff[i] = (size_t)(n0 + row) * ldb + kc * 8;
        dst[i]  = (uint32_t)(row * PITCH + kc * 16);
    }

    auto load_stage = [&](int t) {
        const uint32_t stg = sb + (t % NSTG) * STAGE;
        const size_t ke = (size_t)t * BK;
#pragma unroll
        for (int i = 0; i < 4; i++) {
            cpa16(stg + OFF_AH + dst[i], Ah + aoff[i] + ke);
            cpa16(stg + OFF_AL + dst[i], Al + aoff[i] + ke);
            cpa16(stg + OFF_BH + dst[i], Bh + boff[i] + ke);
        }
        asm volatile("cp.async.commit_group;" ::: "memory");
    };

    const int wm = (wid >> 2) * 64;
    const int wn = (wid & 3) * 32;

    float acc[4][4][4];
#pragma unroll
    for (int mi = 0; mi < 4; mi++)
#pragma unroll
        for (int ni = 0; ni < 4; ni++)
#pragma unroll
            for (int q = 0; q < 4; q++) acc[mi][ni][q] = 0.f;

    const int nt = K / BK;
    load_stage(0);
    if (nt > 1) load_stage(1);

    for (int t = 0; t < nt; t++) {
        if (t < nt - 1) asm volatile("cp.async.wait_group 1;" ::: "memory");
        else            asm volatile("cp.async.wait_group 0;" ::: "memory");
        __syncthreads();
        if (t + 2 < nt) load_stage(t + 2);

        const uint32_t stg = sb + (t % NSTG) * STAGE;
#pragma unroll
        for (int ks = 0; ks < 4; ks++) {
            const int kb = ks * 16;
            uint32_t ah[4][4], al[4][4], bh[2][4];
#pragma unroll
            for (int mi = 0; mi < 4; mi++) {
                const uint32_t ao =
                    (uint32_t)((wm + mi * 16 + (lane & 15)) * PITCH + (kb + (lane >> 4) * 8) * 2);
                ldm_x4(ah[mi], stg + OFF_AH + ao);
                ldm_x4(al[mi], stg + OFF_AL + ao);
            }
#pragma unroll
            for (int np = 0; np < 2; np++) {
                const uint32_t bo =
                    (uint32_t)((wn + np * 16 + (lane >> 4) * 8 + (lane & 7)) * PITCH
                               + (kb + ((lane >> 3) & 1) * 8) * 2);
                ldm_x4(bh[np], stg + OFF_BH + bo);
            }
#pragma unroll
            for (int mi = 0; mi < 4; mi++)
#pragma unroll
                for (int ni = 0; ni < 4; ni++) {
                    mma16816(acc[mi][ni], ah[mi], &bh[ni >> 1][(ni & 1) * 2]);
                    mma16816(acc[mi][ni], al[mi], &bh[ni >> 1][(ni & 1) * 2]);
                }
        }
        if (t + 1 < nt) __syncthreads();
    }

    // ---------------- epilogue ----------------
    float*       C  = WC ? (Cb + (size_t)z * sC) : nullptr;
    fp16*        Ch = SPLIT ? (Chb + (size_t)z * sC) : nullptr;
    fp16*        Cl = SPLIT ? (Clb + (size_t)z * sC) : nullptr;
    const float* bias = (EPI >= 1) ? (biasb + (size_t)(z % bMod) * sBias) : nullptr;
    const fp16*  resh = (EPI == 3) ? (reshb + (size_t)z * sC) : nullptr;
    const fp16*  resl = (EPI == 3) ? (reslb + (size_t)z * sC) : nullptr;

#pragma unroll
    for (int mi = 0; mi < 4; mi++) {
        const int mA = m0 + wm + mi * 16 + (lane >> 2);
        const int mB = mA + 8;
        const size_t coA = ((size_t)(mA >> 6)) * cRowBlk + (size_t)(mA & 63) * ldc;
        const size_t coB = ((size_t)(mB >> 6)) * cRowBlk + (size_t)(mB & 63) * ldc;
#pragma unroll
        for (int ni = 0; ni < 4; ni++) {
            const int col = n0 + wn + ni * 8 + (lane & 3) * 2;
            float2 v0 = make_float2(acc[mi][ni][0], acc[mi][ni][1]);
            float2 v1 = make_float2(acc[mi][ni][2], acc[mi][ni][3]);
            if (EPI >= 1) {
                const float2 bb = *reinterpret_cast<const float2*>(&bias[col]);
                v0.x += bb.x; v0.y += bb.y; v1.x += bb.x; v1.y += bb.y;
            }
            if (EPI == 3) {
                const __half2 hA = *reinterpret_cast<const __half2*>(&resh[coA + col]);
                const __half2 lA = *reinterpret_cast<const __half2*>(&resl[coA + col]);
                const __half2 hB = *reinterpret_cast<const __half2*>(&resh[coB + col]);
                const __half2 lB = *reinterpret_cast<const __half2*>(&resl[coB + col]);
                v0.x += __half2float(hA.x) + __half2float(lA.x);
                v0.y += __half2float(hA.y) + __half2float(lA.y);
                v1.x += __half2float(hB.x) + __half2float(lB.x);
                v1.y += __half2float(hB.y) + __half2float(lB.y);
            }
            if (WC) {
                *reinterpret_cast<float2*>(&C[coA + col]) = v0;
                *reinterpret_cast<float2*>(&C[coB + col]) = v1;
            }
            if (SPLIT) {
                fp16 h0 = __float2half_rn(v0.x), h1 = __float2half_rn(v0.y);
                fp16 h2 = __float2half_rn(v1.x), h3 = __float2half_rn(v1.y);
                *reinterpret_cast<__half2*>(&Ch[coA + col]) = __halves2half2(h0, h1);
                *reinterpret_cast<__half2*>(&Ch[coB + col]) = __halves2half2(h2, h3);
                *reinterpret_cast<__half2*>(&Cl[coA + col]) = __halves2half2(
                    __float2half_rn(v0.x - __half2float(h0)),
                    __float2half_rn(v0.y - __half2float(h1)));
                *reinterpret_cast<__half2*>(&Cl[coB + col]) = __halves2half2(
                    __float2half_rn(v1.x - __half2float(h2)),
                    __float2half_rn(v1.y - __half2float(h3)));
            }
        }
    }
}

// ================= fused x split (row hi/lo + transposed hi) =================
// in [Z][R,C] fp32 -> oh/ol [Z][R,C] fp16, oT [Z][C,R] fp16 hi
__global__ void split_rt_k(const float* __restrict__ in, fp16* __restrict__ oh,
                           fp16* __restrict__ ol, fp16* __restrict__ oT, int R, int C)
{
    __shared__ float t[32][33];
    const size_t zo = (size_t)blockIdx.z * R * C;
    const int c0 = blockIdx.x * 32, r0 = blockIdx.y * 32;
    const int lx = threadIdx.x & 31, ly = threadIdx.x >> 5;
#pragma unroll
    for (int i = 0; i < 4; i++) {
        const int r = ly + 8 * i;
        const float v = in[zo + (size_t)(r0 + r) * C + c0 + lx];
        t[r][lx] = v;
        const size_t o = zo + (size_t)(r0 + r) * C + c0 + lx;
        fp16 h = __float2half_rn(v);
        oh[o] = h;
        ol[o] = __float2half_rn(v - __half2float(h));
    }
    __syncthreads();
#pragma unroll
    for (int i = 0; i < 4; i++) {
        const int c = ly + 8 * i;
        oT[zo + (size_t)(c0 + c) * R + r0 + lx] = __float2half_rn(t[lx][c]);
    }
}

// in [Z][R,C] fp32 -> out [Z][C,R] fp16 hi only
__global__ void splitT_k(const float* __restrict__ in, fp16* __restrict__ oh, int R, int C)
{
    __shared__ float t[32][33];
    const size_t zo = (size_t)blockIdx.z * R * C;
    const int c0 = blockIdx.x * 32, r0 = blockIdx.y * 32;
    const int lx = threadIdx.x & 31, ly = threadIdx.x >> 5;
#pragma unroll
    for (int i = 0; i < 4; i++)
        t[ly + 8 * i][lx] = in[zo + (size_t)(r0 + ly + 8 * i) * C + c0 + lx];
    __syncthreads();
#pragma unroll
    for (int i = 0; i < 4; i++) {
        const int c = ly + 8 * i;
        oh[zo + (size_t)(c0 + c) * R + r0 + lx] = __float2half_rn(t[lx][c]);
    }
}

// ========== fused dispatch softmax (over tokens) + transpose + fp16 split ==========
// w [B][N][ES] -> oh/ol [B][ES][N]
__global__ void dispatch_fused_k(const float* __restrict__ w,
                                 fp16* __restrict__ oh, fp16* __restrict__ ol)
{
    const int b = blockIdx.y, lane = threadIdx.x & 31, grp = threadIdx.x >> 5;
    const int col0 = blockIdx.x * 32;
    const float* p = w + (size_t)b * Nq * ESq + col0;

    __shared__ float red[8][33];
    __shared__ float mcol[32], icol[32];
    __shared__ float t[32][33];

    float mx = -1e30f;
    for (int n = grp; n < Nq; n += 8) mx = fmaxf(mx, p[(size_t)n * ESq + lane]);
    red[grp][lane] = mx;
    __syncthreads();
    if (grp == 0) {
        float m = red[0][lane];
#pragma unroll
        for (int g = 1; g < 8; g++) m = fmaxf(m, red[g][lane]);
        mcol[lane] = m;
    }
    __syncthreads();
    const float m = mcol[lane];
    float s = 0.f;
    for (int n = grp; n < Nq; n += 8) s += __expf(p[(size_t)n * ESq + lane] - m);
    red[grp][lane] = s;
    __syncthreads();
    if (grp == 0) {
        float t2 = red[0][lane];
#pragma unroll
        for (int g = 1; g < 8; g++) t2 += red[g][lane];
        icol[lane] = 1.f / t2;
    }
    __syncthreads();

    const size_t obase = (size_t)b * ESq * Nq;
    for (int n0 = 0; n0 < Nq; n0 += 32) {
#pragma unroll
        for (int i = 0; i < 4; i++) {
            const int r = grp * 4 + i;
            t[r][lane] = p[(size_t)(n0 + r) * ESq + lane];
        }
        __syncthreads();
#pragma unroll
        for (int i = 0; i < 4; i++) {
            const int cc = grp * 4 + i;
            const float val = __expf(t[lane][cc] - mcol[cc]) * icol[cc];
            const size_t o = obase + (size_t)(col0 + cc) * Nq + n0 + lane;
            fp16 h = __float2half_rn(val);
            oh[o] = h;
            ol[o] = __float2half_rn(val - __half2float(h));
        }
        __syncthreads();
    }
}

// ================= combine softmax (row) -> fp16 split =================
__global__ void row_softmax_split_k(const float* __restrict__ w,
                                    fp16* __restrict__ oh, fp16* __restrict__ ol)
{
    const size_t r = blockIdx.x;
    const float* p = w + r * ESq;
    const int tid = threadIdx.x;
    __shared__ float buf[256];

    float v[4];
    float mx = -1e30f;
#pragma unroll
    for (int j = 0; j < 4; j++) { v[j] = p[tid + 256 * j]; mx = fmaxf(mx, v[j]); }
    buf[tid] = mx;
    __syncthreads();
    for (int off = 128; off > 0; off >>= 1) {
        if (tid < off) buf[tid] = fmaxf(buf[tid], buf[tid + off]);
        __syncthreads();
    }
    const float m = buf[0];
    __syncthreads();
    float s = 0.f;
#pragma unroll
    for (int j = 0; j < 4; j++) { v[j] = __expf(v[j] - m); s += v[j]; }
    buf[tid] = s;
    __syncthreads();
    for (int off = 128; off > 0; off >>= 1) {
        if (tid < off) buf[tid] += buf[tid + off];
        __syncthreads();
    }
    const float inv = 1.f / buf[0];
#pragma unroll
    for (int j = 0; j < 4; j++) {
        const float val = v[j] * inv;
        fp16 h = __float2half_rn(val);
        oh[r * ESq + tid + 256 * j] = h;
        ol[r * ESq + tid + 256 * j] = __float2half_rn(val - __half2float(h));
    }
}

// ===== LN + relu + residual: x2 = (xinH+xinL) + relu(LN(h)); emit fp16 hi/lo =====
__global__ void ln_relu_k(const float* __restrict__ h,
                          const fp16* __restrict__ xh, const fp16* __restrict__ xl,
                          const float* __restrict__ g, const float* __restrict__ be,
                          fp16* __restrict__ oh, fp16* __restrict__ ol)
{
    const int r = blockIdx.x;
    const int e = (r / Sq) % Eq;
    const float* hr = h + (size_t)r * Dq;
    const int tid = threadIdx.x;
    __shared__ float rs[256], rs2[256];

    float v[4];
    float s = 0.f, s2 = 0.f;
#pragma unroll
    for (int j = 0; j < 4; j++) {
        v[j] = hr[tid + 256 * j];
        s += v[j]; s2 += v[j] * v[j];
    }
    rs[tid] = s; rs2[tid] = s2;
    __syncthreads();
    for (int off = 128; off > 0; off >>= 1) {
        if (tid < off) { rs[tid] += rs[tid + off]; rs2[tid] += rs2[tid + off]; }
        __syncthreads();
    }
    const float mean = rs[0] * (1.f / Dq);
    const float var  = rs2[0] * (1.f / Dq) - mean * mean;
    const float rstd = rsqrtf(var + EPSq);

#pragma unroll
    for (int j = 0; j < 4; j++) {
        const int d = tid + 256 * j;
        const size_t o = (size_t)r * Dq + d;
        const float xr = __half2float(xh[o]) + __half2float(xl[o]);
        const float ln = (v[j] - mean) * rstd * g[(size_t)e * Dq + d] + be[(size_t)e * Dq + d];
        const float val = xr + fmaxf(ln, 0.f);
        fp16 hh = __float2half_rn(val);
        oh[o] = hh;
        ol[o] = __float2half_rn(val - __half2float(hh));
    }
}

// ================= launch =================
extern "C" void kernel_launch(void* const* d_in, const int* in_sizes, int n_in,
                              void* d_out, int out_size)
{
    const float* x   = (const float*)d_in[0];
    const float* phi = (const float*)d_in[1];
    const float* W1  = (const float*)d_in[2];
    const float* b1  = (const float*)d_in[3];
    const float* g1  = (const float*)d_in[4];
    const float* be1 = (const float*)d_in[5];
    const float* W2  = (const float*)d_in[6];
    const float* b2  = (const float*)d_in[7];
    float* out = (float*)d_out;

    cudaFuncSetAttribute(mma_gemm_k<0,1,0>, cudaFuncAttributeMaxDynamicSharedMemorySize, SMEM_DYN);
    cudaFuncSetAttribute(mma_gemm_k<0,0,1>, cudaFuncAttributeMaxDynamicSharedMemorySize, SMEM_DYN);
    cudaFuncSetAttribute(mma_gemm_k<1,1,0>, cudaFuncAttributeMaxDynamicSharedMemorySize, SMEM_DYN);
    cudaFuncSetAttribute(mma_gemm_k<3,1,0>, cudaFuncAttributeMaxDynamicSharedMemorySize, SMEM_DYN);

    float *w, *h, *y;
    cudaGetSymbolAddress((void**)&w, g_w);
    cudaGetSymbolAddress((void**)&h, g_h);
    cudaGetSymbolAddress((void**)&y, g_y);

    fp16 *xs_h,*xs_l,*xT_h,*phiT_h,*W1T_h,*W2T_h;
    fp16 *dspT_h,*dspT_l,*xinS_h,*xinS_l,*x2S_h,*x2S_l,*yT_h,*cmb_h,*cmb_l;
    cudaGetSymbolAddress((void**)&xs_h, g_xs_h);   cudaGetSymbolAddress((void**)&xs_l, g_xs_l);
    cudaGetSymbolAddress((void**)&xT_h, g_xT_h);
    cudaGetSymbolAddress((void**)&phiT_h, g_phiT_h);
    cudaGetSymbolAddress((void**)&W1T_h, g_W1T_h);
    cudaGetSymbolAddress((void**)&W2T_h, g_W2T_h);
    cudaGetSymbolAddress((void**)&dspT_h, g_dspT_h); cudaGetSymbolAddress((void**)&dspT_l, g_dspT_l);
    cudaGetSymbolAddress((void**)&xinS_h, g_xinS_h); cudaGetSymbolAddress((void**)&xinS_l, g_xinS_l);
    cudaGetSymbolAddress((void**)&x2S_h, g_x2S_h); cudaGetSymbolAddress((void**)&x2S_l, g_x2S_l);
    cudaGetSymbolAddress((void**)&yT_h, g_yT_h);
    cudaGetSymbolAddress((void**)&cmb_h, g_cmb_h); cudaGetSymbolAddress((void**)&cmb_l, g_cmb_l);

    const size_t EXP = (size_t)Eq * Sq * Dq;

    // conversions
    split_rt_k<<<dim3(Dq/32, Nq/32, Bq), 256>>>(x, xs_h, xs_l, xT_h, Nq, Dq);
    splitT_k<<<dim3(ESq/32, Dq/32, 1), 256>>>(phi, phiT_h, Dq, ESq);
    splitT_k<<<dim3(Dq/32, Dq/32, Eq), 256>>>(W1, W1T_h, Dq, Dq);
    splitT_k<<<dim3(Dq/32, Dq/32, Eq), 256>>>(W2, W2T_h, Dq, Dq);

    // K1: w[b] = x[b] @ phi    M=2048 N=1024 K=1024
    mma_gemm_k<0,1,0><<<dim3(ESq/BN, Nq/BM, Bq), 256, SMEM_DYN>>>(
        xs_h, xs_l, phiT_h, nullptr, nullptr, nullptr, w, nullptr, nullptr,
        Dq, Dq, Dq, ESq,
        (size_t)Nq*Dq, 0, (size_t)Nq*ESq, 1, 0,
        (size_t)64*Dq, (size_t)64*ESq);

    // fused dispatch softmax + transpose + split
    dispatch_fused_k<<<dim3(ESq/32, Bq), 256>>>(w, dspT_h, dspT_l);

    // K3: xin[b] = dsp[b]^T @ x[b]   M=1024 N=1024 K=2048  (fp16 hi/lo out only)
    mma_gemm_k<0,0,1><<<dim3(Dq/BN, ESq/BM, Bq), 256, SMEM_DYN>>>(
        dspT_h, dspT_l, xT_h, nullptr, nullptr, nullptr, nullptr, xinS_h, xinS_l,
        Nq, Nq, Nq, Dq,
        (size_t)ESq*Nq, (size_t)Dq*Nq, (size_t)ESq*Dq, Bq, 0,
        (size_t)64*Nq, (size_t)64*Dq);

    // K4: h[e] = xin_e @ W1[e] + b1[e]   M=512 N=1024 K=1024, z=e
    mma_gemm_k<1,1,0><<<dim3(Dq/BN, (Bq*Sq)/BM, Eq), 256, SMEM_DYN>>>(
        xinS_h, xinS_l, W1T_h, b1, nullptr, nullptr, h, nullptr, nullptr,
        Dq, Dq, Dq, Dq,
        (size_t)Sq*Dq, (size_t)Dq*Dq, (size_t)Sq*Dq, Eq, (size_t)Dq,
        EXP, EXP);

    // LN + relu + residual
    ln_relu_k<<<Bq*Eq*Sq, 256>>>(h, xinS_h, xinS_l, g1, be1, x2S_h, x2S_l);

    // K6: y[e] = x2 + x2_e @ W2[e] + b2[e]  (res reconstructed from hi/lo)
    mma_gemm_k<3,1,0><<<dim3(Dq/BN, (Bq*Sq)/BM, Eq), 256, SMEM_DYN>>>(
        x2S_h, x2S_l, W2T_h, b2, x2S_h, x2S_l, y, nullptr, nullptr,
        Dq, Dq, Dq, Dq,
        (size_t)Sq*Dq, (size_t)Dq*Dq, (size_t)Sq*Dq, Eq, (size_t)Dq,
        EXP, EXP);

    // transpose y for K8's B operand (hi only)
    splitT_k<<<dim3(Dq/32, ESq/32, Bq), 256>>>(y, yT_h, ESq, Dq);

    // combine softmax -> split fp16
    row_softmax_split_k<<<Bq*Nq, 256>>>(w, cmb_h, cmb_l);

    // K8: out[b] = cmb[b] @ y[b]   M=2048 N=1024 K=1024
    mma_gemm_k<0,1,0><<<dim3(Dq/BN, Nq/BM, Bq), 256, SMEM_DYN>>>(
        cmb_h, cmb_l, yT_h, nullptr, nullptr, nullptr, out, nullptr, nullptr,
        ESq, ESq, ESq, Dq,
        (size_t)Nq*ESq, (size_t)Dq*ESq, (size_t)Nq*Dq, Bq, 0,
        (size_t)64*ESq, (size_t)64*Dq);
}

// round 7
// speedup vs baseline: 7.4319x; 1.5265x over previous
#include <cuda_runtime.h>
#include <cuda_fp16.h>
#include <math.h>
#include <stdint.h>

typedef __half fp16;

#define Bq   8
#define Nq   2048
#define Dq   1024
#define Eq   16
#define Sq   64
#define ESq  1024
#define EPSq 1e-5f

// ---------------- fp32 scratch ----------------
__device__ __align__(16) float g_w  [(size_t)Bq * Nq * ESq];
__device__ __align__(16) float g_h  [(size_t)Bq * Eq * Sq * Dq];
__device__ __align__(16) float g_y  [(size_t)Bq * Eq * Sq * Dq];

// ---------------- fp16 scratch ----------------
__device__ __align__(16) fp16 g_xs_h [(size_t)Bq * Nq * Dq];
__device__ __align__(16) fp16 g_xT_h [(size_t)Bq * Dq * Nq];
__device__ __align__(16) fp16 g_phiT_h[(size_t)ESq * Dq];
__device__ __align__(16) fp16 g_W1T_h[(size_t)Eq * Dq * Dq];
__device__ __align__(16) fp16 g_W2T_h[(size_t)Eq * Dq * Dq];
__device__ __align__(16) fp16 g_dspT_h[(size_t)Bq * ESq * Nq];
__device__ __align__(16) fp16 g_xinS_h[(size_t)Bq * Eq * Sq * Dq], g_xinS_l[(size_t)Bq * Eq * Sq * Dq];
__device__ __align__(16) fp16 g_x2S_h[(size_t)Bq * Eq * Sq * Dq],  g_x2S_l[(size_t)Bq * Eq * Sq * Dq];
__device__ __align__(16) fp16 g_yT_h [(size_t)Bq * Dq * ESq];
__device__ __align__(16) fp16 g_cmb_h[(size_t)Bq * Nq * ESq];

// ================= mma.sync GEMM (single-term fp16) =================
#define BM 128
#define BN 128
#define BK 64
#define NSTG 4
#define PITCH 144                    // 64 fp16 = 128B + 16B pad
#define HALF_BYTES (128 * PITCH)     // 18432
#define OFF_AH 0
#define OFF_BH HALF_BYTES
#define STAGE  (2 * HALF_BYTES)      // 36864
#define SMEM_DYN (NSTG * STAGE)      // 147456

__device__ __forceinline__ uint32_t s2u(const void* p) {
    uint32_t a;
    asm("{ .reg .u64 t; cvta.to.shared.u64 t, %1; cvt.u32.u64 %0, t; }" : "=r"(a) : "l"(p));
    return a;
}
__device__ __forceinline__ void cpa16(uint32_t dst, const void* src) {
    asm volatile("cp.async.cg.shared.global [%0], [%1], 16;" :: "r"(dst), "l"(src));
}
__device__ __forceinline__ void ldm_x4(uint32_t* r, uint32_t a) {
    asm volatile("ldmatrix.sync.aligned.m8n8.x4.shared.b16 {%0,%1,%2,%3}, [%4];"
                 : "=r"(r[0]), "=r"(r[1]), "=r"(r[2]), "=r"(r[3]) : "r"(a));
}
__device__ __forceinline__ void mma16816(float* c, const uint32_t* a, const uint32_t* b) {
    asm volatile(
        "mma.sync.aligned.m16n8k16.row.col.f32.f16.f16.f32 "
        "{%0,%1,%2,%3}, {%4,%5,%6,%7}, {%8,%9}, {%0,%1,%2,%3};"
        : "+f"(c[0]), "+f"(c[1]), "+f"(c[2]), "+f"(c[3])
        : "r"(a[0]), "r"(a[1]), "r"(a[2]), "r"(a[3]), "r"(b[0]), "r"(b[1]));
}

// C[z] = Ah[z] @ Bh[z%bMod]^T.  A rows: (r>>6)*aRowBlk + (r&63)*lda; C likewise.
// EPI: 0 none, 1 +bias[col], 3 +bias[col] + (resh+resl)[row,col]
// WC: write fp32 C.  SPLIT: write fp16 hi/lo of result.
template<int EPI, int WC, int SPLIT>
__global__ void __launch_bounds__(256, 1)
mma_gemm_k(const fp16* __restrict__ Ahb, const fp16* __restrict__ Bhb,
           const float* __restrict__ biasb,
           const fp16* __restrict__ reshb, const fp16* __restrict__ reslb,
           float* __restrict__ Cb, fp16* __restrict__ Chb, fp16* __restrict__ Clb,
           int K, int lda, int ldb, int ldc,
           size_t sA, size_t sB, size_t sC, int bMod, size_t sBias,
           size_t aRowBlk, size_t cRowBlk)
{
    extern __shared__ char sm[];
    const uint32_t sb = s2u(sm);
    const int tid = threadIdx.x, wid = tid >> 5, lane = tid & 31;
    const int z = blockIdx.z;

    const fp16* Ah = Ahb + (size_t)z * sA;
    const fp16* Bh = Bhb + (size_t)(z % bMod) * sB;

    const int m0 = blockIdx.y * BM;
    const int n0 = blockIdx.x * BN;

    // cp.async maps: 128 rows x 8 chunks(16B) per operand; 4 chunks/thread
    size_t aoff[4], boff[4];
    uint32_t dst[4];
#pragma unroll
    for (int i = 0; i < 4; i++) {
        const int idx = tid + i * 256;
        const int row = idx >> 3, kc = idx & 7;
        const int m = m0 + row;
        aoff[i] = ((size_t)(m >> 6)) * aRowBlk + (size_t)(m & 63) * lda + kc * 8;
        boff[i] = (size_t)(n0 + row) * ldb + kc * 8;
        dst[i]  = (uint32_t)(row * PITCH + kc * 16);
    }

    auto load_stage = [&](int t) {
        const uint32_t stg = sb + (t % NSTG) * STAGE;
        const size_t ke = (size_t)t * BK;
#pragma unroll
        for (int i = 0; i < 4; i++) {
            cpa16(stg + OFF_AH + dst[i], Ah + aoff[i] + ke);
            cpa16(stg + OFF_BH + dst[i], Bh + boff[i] + ke);
        }
        asm volatile("cp.async.commit_group;" ::: "memory");
    };

    const int wm = (wid >> 2) * 64;
    const int wn = (wid & 3) * 32;

    float acc[4][4][4];
#pragma unroll
    for (int mi = 0; mi < 4; mi++)
#pragma unroll
        for (int ni = 0; ni < 4; ni++)
#pragma unroll
            for (int q = 0; q < 4; q++) acc[mi][ni][q] = 0.f;

    const int nt = K / BK;
#pragma unroll
    for (int t = 0; t < NSTG - 1; t++)
        if (t < nt) load_stage(t);

    for (int t = 0; t < nt; t++) {
        const int rem = nt - 1 - t;
        if (rem >= 2)      asm volatile("cp.async.wait_group 2;" ::: "memory");
        else if (rem == 1) asm volatile("cp.async.wait_group 1;" ::: "memory");
        else               asm volatile("cp.async.wait_group 0;" ::: "memory");
        __syncthreads();
        if (t + NSTG - 1 < nt) load_stage(t + NSTG - 1);

        const uint32_t stg = sb + (t % NSTG) * STAGE;
#pragma unroll
        for (int ks = 0; ks < 4; ks++) {
            const int kb = ks * 16;
            uint32_t ah[4][4], bh[2][4];
#pragma unroll
            for (int mi = 0; mi < 4; mi++) {
                const uint32_t ao =
                    (uint32_t)((wm + mi * 16 + (lane & 15)) * PITCH + (kb + (lane >> 4) * 8) * 2);
                ldm_x4(ah[mi], stg + OFF_AH + ao);
            }
#pragma unroll
            for (int np = 0; np < 2; np++) {
                const uint32_t bo =
                    (uint32_t)((wn + np * 16 + (lane >> 4) * 8 + (lane & 7)) * PITCH
                               + (kb + ((lane >> 3) & 1) * 8) * 2);
                ldm_x4(bh[np], stg + OFF_BH + bo);
            }
#pragma unroll
            for (int mi = 0; mi < 4; mi++)
#pragma unroll
                for (int ni = 0; ni < 4; ni++)
                    mma16816(acc[mi][ni], ah[mi], &bh[ni >> 1][(ni & 1) * 2]);
        }
        if (t + 1 < nt) __syncthreads();
    }

    // ---------------- epilogue ----------------
    float*       C  = WC ? (Cb + (size_t)z * sC) : nullptr;
    fp16*        Ch = SPLIT ? (Chb + (size_t)z * sC) : nullptr;
    fp16*        Cl = SPLIT ? (Clb + (size_t)z * sC) : nullptr;
    const float* bias = (EPI >= 1) ? (biasb + (size_t)(z % bMod) * sBias) : nullptr;
    const fp16*  resh = (EPI == 3) ? (reshb + (size_t)z * sC) : nullptr;
    const fp16*  resl = (EPI == 3) ? (reslb + (size_t)z * sC) : nullptr;

#pragma unroll
    for (int mi = 0; mi < 4; mi++) {
        const int mA = m0 + wm + mi * 16 + (lane >> 2);
        const int mB = mA + 8;
        const size_t coA = ((size_t)(mA >> 6)) * cRowBlk + (size_t)(mA & 63) * ldc;
        const size_t coB = ((size_t)(mB >> 6)) * cRowBlk + (size_t)(mB & 63) * ldc;
#pragma unroll
        for (int ni = 0; ni < 4; ni++) {
            const int col = n0 + wn + ni * 8 + (lane & 3) * 2;
            float2 v0 = make_float2(acc[mi][ni][0], acc[mi][ni][1]);
            float2 v1 = make_float2(acc[mi][ni][2], acc[mi][ni][3]);
            if (EPI >= 1) {
                const float2 bb = *reinterpret_cast<const float2*>(&bias[col]);
                v0.x += bb.x; v0.y += bb.y; v1.x += bb.x; v1.y += bb.y;
            }
            if (EPI == 3) {
                const __half2 hA = *reinterpret_cast<const __half2*>(&resh[coA + col]);
                const __half2 lA = *reinterpret_cast<const __half2*>(&resl[coA + col]);
                const __half2 hB = *reinterpret_cast<const __half2*>(&resh[coB + col]);
                const __half2 lB = *reinterpret_cast<const __half2*>(&resl[coB + col]);
                v0.x += __half2float(hA.x) + __half2float(lA.x);
                v0.y += __half2float(hA.y) + __half2float(lA.y);
                v1.x += __half2float(hB.x) + __half2float(lB.x);
                v1.y += __half2float(hB.y) + __half2float(lB.y);
            }
            if (WC) {
                *reinterpret_cast<float2*>(&C[coA + col]) = v0;
                *reinterpret_cast<float2*>(&C[coB + col]) = v1;
            }
            if (SPLIT) {
                fp16 h0 = __float2half_rn(v0.x), h1 = __float2half_rn(v0.y);
                fp16 h2 = __float2half_rn(v1.x), h3 = __float2half_rn(v1.y);
                *reinterpret_cast<__half2*>(&Ch[coA + col]) = __halves2half2(h0, h1);
                *reinterpret_cast<__half2*>(&Ch[coB + col]) = __halves2half2(h2, h3);
                *reinterpret_cast<__half2*>(&Cl[coA + col]) = __halves2half2(
                    __float2half_rn(v0.x - __half2float(h0)),
                    __float2half_rn(v0.y - __half2float(h1)));
                *reinterpret_cast<__half2*>(&Cl[coB + col]) = __halves2half2(
                    __float2half_rn(v1.x - __half2float(h2)),
                    __float2half_rn(v1.y - __half2float(h3)));
            }
        }
    }
}

// ====== fused x conversion: row-major fp16 + transposed fp16 ======
__global__ void split_rt_k(const float* __restrict__ in, fp16* __restrict__ oh,
                           fp16* __restrict__ oT, int R, int C)
{
    __shared__ float t[32][33];
    const size_t zo = (size_t)blockIdx.z * R * C;
    const int c0 = blockIdx.x * 32, r0 = blockIdx.y * 32;
    const int lx = threadIdx.x & 31, ly = threadIdx.x >> 5;
#pragma unroll
    for (int i = 0; i < 4; i++) {
        const int r = ly + 8 * i;
        const float v = in[zo + (size_t)(r0 + r) * C + c0 + lx];
        t[r][lx] = v;
        oh[zo + (size_t)(r0 + r) * C + c0 + lx] = __float2half_rn(v);
    }
    __syncthreads();
#pragma unroll
    for (int i = 0; i < 4; i++) {
        const int c = ly + 8 * i;
        oT[zo + (size_t)(c0 + c) * R + r0 + lx] = __float2half_rn(t[lx][c]);
    }
}

// in [Z][R,C] fp32 -> out [Z][C,R] fp16
__global__ void splitT_k(const float* __restrict__ in, fp16* __restrict__ oh, int R, int C)
{
    __shared__ float t[32][33];
    const size_t zo = (size_t)blockIdx.z * R * C;
    const int c0 = blockIdx.x * 32, r0 = blockIdx.y * 32;
    const int lx = threadIdx.x & 31, ly = threadIdx.x >> 5;
#pragma unroll
    for (int i = 0; i < 4; i++)
        t[ly + 8 * i][lx] = in[zo + (size_t)(r0 + ly + 8 * i) * C + c0 + lx];
    __syncthreads();
#pragma unroll
    for (int i = 0; i < 4; i++) {
        const int c = ly + 8 * i;
        oh[zo + (size_t)(c0 + c) * R + r0 + lx] = __float2half_rn(t[lx][c]);
    }
}

// ====== fused dispatch softmax (over tokens) + transpose -> fp16 ======
__global__ void dispatch_fused_k(const float* __restrict__ w, fp16* __restrict__ oh)
{
    const int b = blockIdx.y, lane = threadIdx.x & 31, grp = threadIdx.x >> 5;
    const int col0 = blockIdx.x * 32;
    const float* p = w + (size_t)b * Nq * ESq + col0;

    __shared__ float red[8][33];
    __shared__ float mcol[32], icol[32];
    __shared__ float t[32][33];

    float mx = -1e30f;
    for (int n = grp; n < Nq; n += 8) mx = fmaxf(mx, p[(size_t)n * ESq + lane]);
    red[grp][lane] = mx;
    __syncthreads();
    if (grp == 0) {
        float m = red[0][lane];
#pragma unroll
        for (int g = 1; g < 8; g++) m = fmaxf(m, red[g][lane]);
        mcol[lane] = m;
    }
    __syncthreads();
    const float m = mcol[lane];
    float s = 0.f;
    for (int n = grp; n < Nq; n += 8) s += __expf(p[(size_t)n * ESq + lane] - m);
    red[grp][lane] = s;
    __syncthreads();
    if (grp == 0) {
        float t2 = red[0][lane];
#pragma unroll
        for (int g = 1; g < 8; g++) t2 += red[g][lane];
        icol[lane] = 1.f / t2;
    }
    __syncthreads();

    const size_t obase = (size_t)b * ESq * Nq;
    for (int n0 = 0; n0 < Nq; n0 += 32) {
#pragma unroll
        for (int i = 0; i < 4; i++) {
            const int r = grp * 4 + i;
            t[r][lane] = p[(size_t)(n0 + r) * ESq + lane];
        }
        __syncthreads();
#pragma unroll
        for (int i = 0; i < 4; i++) {
            const int cc = grp * 4 + i;
            const float val = __expf(t[lane][cc] - mcol[cc]) * icol[cc];
            oh[obase + (size_t)(col0 + cc) * Nq + n0 + lane] = __float2half_rn(val);
        }
        __syncthreads();
    }
}

// ================= combine softmax (row) -> fp16 =================
__global__ void row_softmax_split_k(const float* __restrict__ w, fp16* __restrict__ oh)
{
    const size_t r = blockIdx.x;
    const float* p = w + r * ESq;
    const int tid = threadIdx.x;
    __shared__ float buf[256];

    float v[4];
    float mx = -1e30f;
#pragma unroll
    for (int j = 0; j < 4; j++) { v[j] = p[tid + 256 * j]; mx = fmaxf(mx, v[j]); }
    buf[tid] = mx;
    __syncthreads();
    for (int off = 128; off > 0; off >>= 1) {
        if (tid < off) buf[tid] = fmaxf(buf[tid], buf[tid + off]);
        __syncthreads();
    }
    const float m = buf[0];
    __syncthreads();
    float s = 0.f;
#pragma unroll
    for (int j = 0; j < 4; j++) { v[j] = __expf(v[j] - m); s += v[j]; }
    buf[tid] = s;
    __syncthreads();
    for (int off = 128; off > 0; off >>= 1) {
        if (tid < off) buf[tid] += buf[tid + off];
        __syncthreads();
    }
    const float inv = 1.f / buf[0];
#pragma unroll
    for (int j = 0; j < 4; j++)
        oh[r * ESq + tid + 256 * j] = __float2half_rn(v[j] * inv);
}

// ===== LN + relu + residual: x2 = (xinH+xinL) + relu(LN(h)); emit fp16 hi/lo =====
__global__ void ln_relu_k(const float* __restrict__ h,
                          const fp16* __restrict__ xh, const fp16* __restrict__ xl,
                          const float* __restrict__ g, const float* __restrict__ be,
                          fp16* __restrict__ oh, fp16* __restrict__ ol)
{
    const int r = blockIdx.x;
    const int e = (r / Sq) % Eq;
    const float* hr = h + (size_t)r * Dq;
    const int tid = threadIdx.x;
    __shared__ float rs[256], rs2[256];

    float v[4];
    float s = 0.f, s2 = 0.f;
#pragma unroll
    for (int j = 0; j < 4; j++) {
        v[j] = hr[tid + 256 * j];
        s += v[j]; s2 += v[j] * v[j];
    }
    rs[tid] = s; rs2[tid] = s2;
    __syncthreads();
    for (int off = 128; off > 0; off >>= 1) {
        if (tid < off) { rs[tid] += rs[tid + off]; rs2[tid] += rs2[tid + off]; }
        __syncthreads();
    }
    const float mean = rs[0] * (1.f / Dq);
    const float var  = rs2[0] * (1.f / Dq) - mean * mean;
    const float rstd = rsqrtf(var + EPSq);

#pragma unroll
    for (int j = 0; j < 4; j++) {
        const int d = tid + 256 * j;
        const size_t o = (size_t)r * Dq + d;
        const float xr = __half2float(xh[o]) + __half2float(xl[o]);
        const float ln = (v[j] - mean) * rstd * g[(size_t)e * Dq + d] + be[(size_t)e * Dq + d];
        const float val = xr + fmaxf(ln, 0.f);
        fp16 hh = __float2half_rn(val);
        oh[o] = hh;
        ol[o] = __float2half_rn(val - __half2float(hh));
    }
}

// ================= launch =================
extern "C" void kernel_launch(void* const* d_in, const int* in_sizes, int n_in,
                              void* d_out, int out_size)
{
    const float* x   = (const float*)d_in[0];
    const float* phi = (const float*)d_in[1];
    const float* W1  = (const float*)d_in[2];
    const float* b1  = (const float*)d_in[3];
    const float* g1  = (const float*)d_in[4];
    const float* be1 = (const float*)d_in[5];
    const float* W2  = (const float*)d_in[6];
    const float* b2  = (const float*)d_in[7];
    float* out = (float*)d_out;

    cudaFuncSetAttribute(mma_gemm_k<0,1,0>, cudaFuncAttributeMaxDynamicSharedMemorySize, SMEM_DYN);
    cudaFuncSetAttribute(mma_gemm_k<0,0,1>, cudaFuncAttributeMaxDynamicSharedMemorySize, SMEM_DYN);
    cudaFuncSetAttribute(mma_gemm_k<1,1,0>, cudaFuncAttributeMaxDynamicSharedMemorySize, SMEM_DYN);
    cudaFuncSetAttribute(mma_gemm_k<3,1,0>, cudaFuncAttributeMaxDynamicSharedMemorySize, SMEM_DYN);

    float *w, *h, *y;
    cudaGetSymbolAddress((void**)&w, g_w);
    cudaGetSymbolAddress((void**)&h, g_h);
    cudaGetSymbolAddress((void**)&y, g_y);

    fp16 *xs_h,*xT_h,*phiT_h,*W1T_h,*W2T_h;
    fp16 *dspT_h,*xinS_h,*xinS_l,*x2S_h,*x2S_l,*yT_h,*cmb_h;
    cudaGetSymbolAddress((void**)&xs_h, g_xs_h);
    cudaGetSymbolAddress((void**)&xT_h, g_xT_h);
    cudaGetSymbolAddress((void**)&phiT_h, g_phiT_h);
    cudaGetSymbolAddress((void**)&W1T_h, g_W1T_h);
    cudaGetSymbolAddress((void**)&W2T_h, g_W2T_h);
    cudaGetSymbolAddress((void**)&dspT_h, g_dspT_h);
    cudaGetSymbolAddress((void**)&xinS_h, g_xinS_h); cudaGetSymbolAddress((void**)&xinS_l, g_xinS_l);
    cudaGetSymbolAddress((void**)&x2S_h, g_x2S_h); cudaGetSymbolAddress((void**)&x2S_l, g_x2S_l);
    cudaGetSymbolAddress((void**)&yT_h, g_yT_h);
    cudaGetSymbolAddress((void**)&cmb_h, g_cmb_h);

    const size_t EXP = (size_t)Eq * Sq * Dq;

    // conversions
    split_rt_k<<<dim3(Dq/32, Nq/32, Bq), 256>>>(x, xs_h, xT_h, Nq, Dq);
    splitT_k<<<dim3(ESq/32, Dq/32, 1), 256>>>(phi, phiT_h, Dq, ESq);
    splitT_k<<<dim3(Dq/32, Dq/32, Eq), 256>>>(W1, W1T_h, Dq, Dq);
    splitT_k<<<dim3(Dq/32, Dq/32, Eq), 256>>>(W2, W2T_h, Dq, Dq);

    // K1: w[b] = x[b] @ phi    M=2048 N=1024 K=1024
    mma_gemm_k<0,1,0><<<dim3(ESq/BN, Nq/BM, Bq), 256, SMEM_DYN>>>(
        xs_h, phiT_h, nullptr, nullptr, nullptr, w, nullptr, nullptr,
        Dq, Dq, Dq, ESq,
        (size_t)Nq*Dq, 0, (size_t)Nq*ESq, 1, 0,
        (size_t)64*Dq, (size_t)64*ESq);

    // fused dispatch softmax + transpose
    dispatch_fused_k<<<dim3(ESq/32, Bq), 256>>>(w, dspT_h);

    // K3: xin[b] = dsp[b]^T @ x[b]   M=1024 N=1024 K=2048  (fp16 hi/lo out)
    mma_gemm_k<0,0,1><<<dim3(Dq/BN, ESq/BM, Bq), 256, SMEM_DYN>>>(
        dspT_h, xT_h, nullptr, nullptr, nullptr, nullptr, xinS_h, xinS_l,
        Nq, Nq, Nq, Dq,
        (size_t)ESq*Nq, (size_t)Dq*Nq, (size_t)ESq*Dq, Bq, 0,
        (size_t)64*Nq, (size_t)64*Dq);

    // K4: h[e] = xin_e @ W1[e] + b1[e]   M=512 N=1024 K=1024, z=e
    mma_gemm_k<1,1,0><<<dim3(Dq/BN, (Bq*Sq)/BM, Eq), 256, SMEM_DYN>>>(
        xinS_h, W1T_h, b1, nullptr, nullptr, h, nullptr, nullptr,
        Dq, Dq, Dq, Dq,
        (size_t)Sq*Dq, (size_t)Dq*Dq, (size_t)Sq*Dq, Eq, (size_t)Dq,
        EXP, EXP);

    // LN + relu + residual
    ln_relu_k<<<Bq*Eq*Sq, 256>>>(h, xinS_h, xinS_l, g1, be1, x2S_h, x2S_l);

    // K6: y[e] = x2 + x2_e @ W2[e] + b2[e]
    mma_gemm_k<3,1,0><<<dim3(Dq/BN, (Bq*Sq)/BM, Eq), 256, SMEM_DYN>>>(
        x2S_h, W2T_h, b2, x2S_h, x2S_l, y, nullptr, nullptr,
        Dq, Dq, Dq, Dq,
        (size_t)Sq*Dq, (size_t)Dq*Dq, (size_t)Sq*Dq, Eq, (size_t)Dq,
        EXP, EXP);

    // transpose y for K8's B operand
    splitT_k<<<dim3(Dq/32, ESq/32, Bq), 256>>>(y, yT_h, ESq, Dq);

    // combine softmax -> fp16
    row_softmax_split_k<<<Bq*Nq, 256>>>(w, cmb_h);

    // K8: out[b] = cmb[b] @ y[b]   M=2048 N=1024 K=1024
    mma_gemm_k<0,1,0><<<dim3(Dq/BN, Nq/BM, Bq), 256, SMEM_DYN>>>(
        cmb_h, yT_h, nullptr, nullptr, nullptr, out, nullptr, nullptr,
        ESq, ESq, ESq, Dq,
        (size_t)Nq*ESq, (size_t)Dq*ESq, (size_t)Nq*Dq, Bq, 0,
        (size_t)64*ESq, (size_t)64*Dq);
}

// round 8
// speedup vs baseline: 8.2764x; 1.1136x over previous
#include <cuda_runtime.h>
#include <cuda_fp16.h>
#include <math.h>
#include <stdint.h>

typedef __half fp16;

#define Bq   8
#define Nq   2048
#define Dq   1024
#define Eq   16
#define Sq   64
#define ESq  1024
#define EPSq 1e-5f

// ---------------- fp32 scratch ----------------
__device__ __align__(16) float g_w  [(size_t)Bq * Nq * ESq];
__device__ __align__(16) float g_h  [(size_t)Bq * Eq * Sq * Dq];

// ---------------- fp16 scratch ----------------
__device__ __align__(16) fp16 g_x16  [(size_t)Bq * Nq * Dq];
__device__ __align__(16) fp16 g_phi16[(size_t)Dq * ESq];
__device__ __align__(16) fp16 g_W116 [(size_t)Eq * Dq * Dq];
__device__ __align__(16) fp16 g_W216 [(size_t)Eq * Dq * Dq];
__device__ __align__(16) fp16 g_dspT [(size_t)Bq * ESq * Nq];
__device__ __align__(16) fp16 g_xin_h[(size_t)Bq * Eq * Sq * Dq], g_xin_l[(size_t)Bq * Eq * Sq * Dq];
__device__ __align__(16) fp16 g_x2_h [(size_t)Bq * Eq * Sq * Dq], g_x2_l [(size_t)Bq * Eq * Sq * Dq];
__device__ __align__(16) fp16 g_y16  [(size_t)Bq * Eq * Sq * Dq];
__device__ __align__(16) fp16 g_cmb  [(size_t)Bq * Nq * ESq];

// ================= mma.sync GEMM: A [M,K] row-major, B [K,N] row-major =================
#define BM 128
#define BN 256
#define BK 64
#define NSTG 3
#define PA 144                        // A row pitch bytes (64 fp16 + pad)
#define PB 528                        // B row pitch bytes (256 fp16 + pad)
#define A_BYTES (128 * PA)            // 18432
#define B_BYTES (64 * PB)             // 33792
#define OFF_A 0
#define OFF_B A_BYTES
#define STAGE (A_BYTES + B_BYTES)     // 52224
#define SMEM_DYN (NSTG * STAGE)       // 156672

__device__ __forceinline__ uint32_t s2u(const void* p) {
    uint32_t a;
    asm("{ .reg .u64 t; cvta.to.shared.u64 t, %1; cvt.u32.u64 %0, t; }" : "=r"(a) : "l"(p));
    return a;
}
__device__ __forceinline__ void cpa16(uint32_t dst, const void* src) {
    asm volatile("cp.async.cg.shared.global [%0], [%1], 16;" :: "r"(dst), "l"(src));
}
__device__ __forceinline__ void ldm_x4(uint32_t* r, uint32_t a) {
    asm volatile("ldmatrix.sync.aligned.m8n8.x4.shared.b16 {%0,%1,%2,%3}, [%4];"
                 : "=r"(r[0]), "=r"(r[1]), "=r"(r[2]), "=r"(r[3]) : "r"(a));
}
__device__ __forceinline__ void ldm_x4t(uint32_t* r, uint32_t a) {
    asm volatile("ldmatrix.sync.aligned.m8n8.x4.trans.shared.b16 {%0,%1,%2,%3}, [%4];"
                 : "=r"(r[0]), "=r"(r[1]), "=r"(r[2]), "=r"(r[3]) : "r"(a));
}
__device__ __forceinline__ void mma16816(float* c, const uint32_t* a, const uint32_t* b) {
    asm volatile(
        "mma.sync.aligned.m16n8k16.row.col.f32.f16.f16.f32 "
        "{%0,%1,%2,%3}, {%4,%5,%6,%7}, {%8,%9}, {%0,%1,%2,%3};"
        : "+f"(c[0]), "+f"(c[1]), "+f"(c[2]), "+f"(c[3])
        : "r"(a[0]), "r"(a[1]), "r"(a[2]), "r"(a[3]), "r"(b[0]), "r"(b[1]));
}

// C[z] = A[z] @ B[z%bMod].  A rows: (r>>6)*aRowBlk + (r&63)*lda; C likewise via cRowBlk.
// EPI: 0 none, 1 +bias[col], 3 +bias[col] + (resh+resl)[row,col]
// WC: write fp32 C.  SPLIT: 0 none, 1 fp16 hi+lo, 2 fp16 hi only.
template<int EPI, int WC, int SPLIT>
__global__ void __launch_bounds__(256, 1)
mma_gemm_k(const fp16* __restrict__ Ab, const fp16* __restrict__ Bb,
           const float* __restrict__ biasb,
           const fp16* __restrict__ reshb, const fp16* __restrict__ reslb,
           float* __restrict__ Cb, fp16* __restrict__ Chb, fp16* __restrict__ Clb,
           int K, int lda, int ldb, int ldc,
           size_t sA, size_t sB, size_t sC, int bMod, size_t sBias,
           size_t aRowBlk, size_t cRowBlk)
{
    extern __shared__ char sm[];
    const uint32_t sb = s2u(sm);
    const int tid = threadIdx.x, wid = tid >> 5, lane = tid & 31;
    const int z = blockIdx.z;

    const fp16* A = Ab + (size_t)z * sA;
    const fp16* B = Bb + (size_t)(z % bMod) * sB;

    const int m0 = blockIdx.y * BM;
    const int n0 = blockIdx.x * BN;

    // A: 1024 chunks (128 rows x 8), 4/thread
    size_t aoff[4]; uint32_t adst[4];
#pragma unroll
    for (int i = 0; i < 4; i++) {
        const int idx = tid + i * 256;
        const int row = idx >> 3, kc = idx & 7;
        const int m = m0 + row;
        aoff[i] = ((size_t)(m >> 6)) * aRowBlk + (size_t)(m & 63) * lda + kc * 8;
        adst[i] = (uint32_t)(row * PA + kc * 16);
    }
    // B: 2048 chunks (64 rows x 32), 8/thread
    size_t boff[8]; uint32_t bdst[8];
#pragma unroll
    for (int i = 0; i < 8; i++) {
        const int idx = tid + i * 256;
        const int row = idx >> 5, nc = idx & 31;
        boff[i] = (size_t)row * ldb + n0 + nc * 8;
        bdst[i] = (uint32_t)(row * PB + nc * 16);
    }

    auto load_stage = [&](int t) {
        const uint32_t stg = sb + (t % NSTG) * STAGE;
        const size_t ke = (size_t)t * BK;
#pragma unroll
        for (int i = 0; i < 4; i++) cpa16(stg + OFF_A + adst[i], A + aoff[i] + ke);
        const size_t kb = ke * ldb;
#pragma unroll
        for (int i = 0; i < 8; i++) cpa16(stg + OFF_B + bdst[i], B + boff[i] + kb);
        asm volatile("cp.async.commit_group;" ::: "memory");
    };

    const int wm = (wid >> 2) * 64;
    const int wn = (wid & 3) * 64;

    float acc[4][8][4];
#pragma unroll
    for (int mi = 0; mi < 4; mi++)
#pragma unroll
        for (int ni = 0; ni < 8; ni++)
#pragma unroll
            for (int q = 0; q < 4; q++) acc[mi][ni][q] = 0.f;

    const int nt = K / BK;
    load_stage(0);
    if (nt > 1) load_stage(1);

    for (int t = 0; t < nt; t++) {
        if (t + 1 < nt) asm volatile("cp.async.wait_group 1;" ::: "memory");
        else            asm volatile("cp.async.wait_group 0;" ::: "memory");
        __syncthreads();
        if (t + 2 < nt) load_stage(t + 2);

        const uint32_t stg = sb + (t % NSTG) * STAGE;
#pragma unroll
        for (int ks = 0; ks < 4; ks++) {
            const int kb = ks * 16;
            uint32_t ah[4][4], bh[4][4];
#pragma unroll
            for (int mi = 0; mi < 4; mi++) {
                const uint32_t ao =
                    (uint32_t)((wm + mi * 16 + (lane & 15)) * PA + (kb + (lane >> 4) * 8) * 2);
                ldm_x4(ah[mi], stg + OFF_A + ao);
            }
#pragma unroll
            for (int nj = 0; nj < 4; nj++) {
                const uint32_t bo =
                    (uint32_t)((kb + (lane & 15)) * PB + (wn + nj * 16 + (lane >> 4) * 8) * 2);
                ldm_x4t(bh[nj], stg + OFF_B + bo);
            }
#pragma unroll
            for (int mi = 0; mi < 4; mi++)
#pragma unroll
                for (int ni = 0; ni < 8; ni++)
                    mma16816(acc[mi][ni], ah[mi], &bh[ni >> 1][(ni & 1) * 2]);
        }
    }

    // ---------------- epilogue ----------------
    float*       C  = WC ? (Cb + (size_t)z * sC) : nullptr;
    fp16*        Ch = SPLIT ? (Chb + (size_t)z * sC) : nullptr;
    fp16*        Cl = (SPLIT == 1) ? (Clb + (size_t)z * sC) : nullptr;
    const float* bias = (EPI >= 1) ? (biasb + (size_t)(z % bMod) * sBias) : nullptr;
    const fp16*  resh = (EPI == 3) ? (reshb + (size_t)z * sC) : nullptr;
    const fp16*  resl = (EPI == 3) ? (reslb + (size_t)z * sC) : nullptr;

#pragma unroll
    for (int mi = 0; mi < 4; mi++) {
        const int mA = m0 + wm + mi * 16 + (lane >> 2);
        const int mB = mA + 8;
        const size_t coA = ((size_t)(mA >> 6)) * cRowBlk + (size_t)(mA & 63) * ldc;
        const size_t coB = ((size_t)(mB >> 6)) * cRowBlk + (size_t)(mB & 63) * ldc;
#pragma unroll
        for (int ni = 0; ni < 8; ni++) {
            const int col = n0 + wn + ni * 8 + (lane & 3) * 2;
            float2 v0 = make_float2(acc[mi][ni][0], acc[mi][ni][1]);
            float2 v1 = make_float2(acc[mi][ni][2], acc[mi][ni][3]);
            if (EPI >= 1) {
                const float2 bb = *reinterpret_cast<const float2*>(&bias[col]);
                v0.x += bb.x; v0.y += bb.y; v1.x += bb.x; v1.y += bb.y;
            }
            if (EPI == 3) {
                const __half2 hA = *reinterpret_cast<const __half2*>(&resh[coA + col]);
                const __half2 lA = *reinterpret_cast<const __half2*>(&resl[coA + col]);
                const __half2 hB = *reinterpret_cast<const __half2*>(&resh[coB + col]);
                const __half2 lB = *reinterpret_cast<const __half2*>(&resl[coB + col]);
                v0.x += __half2float(hA.x) + __half2float(lA.x);
                v0.y += __half2float(hA.y) + __half2float(lA.y);
                v1.x += __half2float(hB.x) + __half2float(lB.x);
                v1.y += __half2float(hB.y) + __half2float(lB.y);
            }
            if (WC) {
                *reinterpret_cast<float2*>(&C[coA + col]) = v0;
                *reinterpret_cast<float2*>(&C[coB + col]) = v1;
            }
            if (SPLIT) {
                fp16 h0 = __float2half_rn(v0.x), h1 = __float2half_rn(v0.y);
                fp16 h2 = __float2half_rn(v1.x), h3 = __float2half_rn(v1.y);
                *reinterpret_cast<__half2*>(&Ch[coA + col]) = __halves2half2(h0, h1);
                *reinterpret_cast<__half2*>(&Ch[coB + col]) = __halves2half2(h2, h3);
                if (SPLIT == 1) {
                    *reinterpret_cast<__half2*>(&Cl[coA + col]) = __halves2half2(
                        __float2half_rn(v0.x - __half2float(h0)),
                        __float2half_rn(v0.y - __half2float(h1)));
                    *reinterpret_cast<__half2*>(&Cl[coB + col]) = __halves2half2(
                        __float2half_rn(v1.x - __half2float(h2)),
                        __float2half_rn(v1.y - __half2float(h3)));
                }
            }
        }
    }
}

// ================= fp32 -> fp16 convert (no transpose) =================
__global__ void convert_k(const float* __restrict__ in, fp16* __restrict__ o, size_t n4)
{
    const size_t i = (size_t)blockIdx.x * blockDim.x + threadIdx.x;
    if (i >= n4) return;
    const float4 v = reinterpret_cast<const float4*>(in)[i];
    __half2 a = __halves2half2(__float2half_rn(v.x), __float2half_rn(v.y));
    __half2 b = __halves2half2(__float2half_rn(v.z), __float2half_rn(v.w));
    reinterpret_cast<__half2*>(o)[2 * i]     = a;
    reinterpret_cast<__half2*>(o)[2 * i + 1] = b;
}

// ====== fused dispatch softmax (over tokens) + transpose -> fp16, 2-pass ======
__global__ void dispatch_fused_k(const float* __restrict__ w, fp16* __restrict__ oh)
{
    const int b = blockIdx.y, lane = threadIdx.x & 31, grp = threadIdx.x >> 5;
    const int col0 = blockIdx.x * 32;
    const float* p = w + (size_t)b * Nq * ESq + col0;

    __shared__ float redm[8][33], reds[8][33];
    __shared__ float mcol[32], icol[32];
    __shared__ float t[32][33];

    // pass 1: online max+sum over tokens (strided by group)
    float m = -1e30f, s = 0.f;
    for (int n = grp; n < Nq; n += 8) {
        const float v = p[(size_t)n * ESq + lane];
        const float nm = fmaxf(m, v);
        s = s * __expf(m - nm) + __expf(v - nm);
        m = nm;
    }
    redm[grp][lane] = m; reds[grp][lane] = s;
    __syncthreads();
    if (grp == 0) {
        float M = redm[0][lane];
#pragma unroll
        for (int g = 1; g < 8; g++) M = fmaxf(M, redm[g][lane]);
        float S = 0.f;
#pragma unroll
        for (int g = 1 - 1; g < 8; g++) S += reds[g][lane] * __expf(redm[g][lane] - M);
        mcol[lane] = M;
        icol[lane] = 1.f / S;
    }
    __syncthreads();

    // pass 2: write transposed fp16
    const size_t obase = (size_t)b * ESq * Nq;
    for (int n0 = 0; n0 < Nq; n0 += 32) {
#pragma unroll
        for (int i = 0; i < 4; i++) {
            const int r = grp * 4 + i;
            t[r][lane] = p[(size_t)(n0 + r) * ESq + lane];
        }
        __syncthreads();
#pragma unroll
        for (int i = 0; i < 4; i++) {
            const int cc = grp * 4 + i;
            const float val = __expf(t[lane][cc] - mcol[cc]) * icol[cc];
            oh[obase + (size_t)(col0 + cc) * Nq + n0 + lane] = __float2half_rn(val);
        }
        __syncthreads();
    }
}

// ================= combine softmax (row) -> fp16 =================
__global__ void row_softmax_k(const float* __restrict__ w, fp16* __restrict__ oh)
{
    const size_t r = blockIdx.x;
    const float* p = w + r * ESq;
    const int tid = threadIdx.x;
    __shared__ float buf[256];

    float v[4];
    float mx = -1e30f;
#pragma unroll
    for (int j = 0; j < 4; j++) { v[j] = p[tid + 256 * j]; mx = fmaxf(mx, v[j]); }
    buf[tid] = mx;
    __syncthreads();
    for (int off = 128; off > 0; off >>= 1) {
        if (tid < off) buf[tid] = fmaxf(buf[tid], buf[tid + off]);
        __syncthreads();
    }
    const float m = buf[0];
    __syncthreads();
    float s = 0.f;
#pragma unroll
    for (int j = 0; j < 4; j++) { v[j] = __expf(v[j] - m); s += v[j]; }
    buf[tid] = s;
    __syncthreads();
    for (int off = 128; off > 0; off >>= 1) {
        if (tid < off) buf[tid] += buf[tid + off];
        __syncthreads();
    }
    const float inv = 1.f / buf[0];
#pragma unroll
    for (int j = 0; j < 4; j++)
        oh[r * ESq + tid + 256 * j] = __float2half_rn(v[j] * inv);
}

// ===== LN + relu + residual: x2 = (xinH+xinL) + relu(LN(h)); emit fp16 hi/lo =====
__global__ void ln_relu_k(const float* __restrict__ h,
                          const fp16* __restrict__ xh, const fp16* __restrict__ xl,
                          const float* __restrict__ g, const float* __restrict__ be,
                          fp16* __restrict__ oh, fp16* __restrict__ ol)
{
    const int r = blockIdx.x;
    const int e = (r / Sq) % Eq;
    const float* hr = h + (size_t)r * Dq;
    const int tid = threadIdx.x;
    __shared__ float rs[256], rs2[256];

    float v[4];
    float s = 0.f, s2 = 0.f;
#pragma unroll
    for (int j = 0; j < 4; j++) {
        v[j] = hr[tid + 256 * j];
        s += v[j]; s2 += v[j] * v[j];
    }
    rs[tid] = s; rs2[tid] = s2;
    __syncthreads();
    for (int off = 128; off > 0; off >>= 1) {
        if (tid < off) { rs[tid] += rs[tid + off]; rs2[tid] += rs2[tid + off]; }
        __syncthreads();
    }
    const float mean = rs[0] * (1.f / Dq);
    const float var  = rs2[0] * (1.f / Dq) - mean * mean;
    const float rstd = rsqrtf(var + EPSq);

#pragma unroll
    for (int j = 0; j < 4; j++) {
        const int d = tid + 256 * j;
        const size_t o = (size_t)r * Dq + d;
        const float xr = __half2float(xh[o]) + __half2float(xl[o]);
        const float ln = (v[j] - mean) * rstd * g[(size_t)e * Dq + d] + be[(size_t)e * Dq + d];
        const float val = xr + fmaxf(ln, 0.f);
        fp16 hh = __float2half_rn(val);
        oh[o] = hh;
        ol[o] = __float2half_rn(val - __half2float(hh));
    }
}

// ================= launch =================
extern "C" void kernel_launch(void* const* d_in, const int* in_sizes, int n_in,
                              void* d_out, int out_size)
{
    const float* x   = (const float*)d_in[0];
    const float* phi = (const float*)d_in[1];
    const float* W1  = (const float*)d_in[2];
    const float* b1  = (const float*)d_in[3];
    const float* g1  = (const float*)d_in[4];
    const float* be1 = (const float*)d_in[5];
    const float* W2  = (const float*)d_in[6];
    const float* b2  = (const float*)d_in[7];
    float* out = (float*)d_out;

    cudaFuncSetAttribute(mma_gemm_k<0,1,0>, cudaFuncAttributeMaxDynamicSharedMemorySize, SMEM_DYN);
    cudaFuncSetAttribute(mma_gemm_k<0,0,1>, cudaFuncAttributeMaxDynamicSharedMemorySize, SMEM_DYN);
    cudaFuncSetAttribute(mma_gemm_k<1,1,0>, cudaFuncAttributeMaxDynamicSharedMemorySize, SMEM_DYN);
    cudaFuncSetAttribute(mma_gemm_k<3,0,2>, cudaFuncAttributeMaxDynamicSharedMemorySize, SMEM_DYN);

    float *w, *h;
    cudaGetSymbolAddress((void**)&w, g_w);
    cudaGetSymbolAddress((void**)&h, g_h);

    fp16 *x16,*phi16,*W116,*W216,*dspT,*xin_h,*xin_l,*x2_h,*x2_l,*y16,*cmb;
    cudaGetSymbolAddress((void**)&x16, g_x16);
    cudaGetSymbolAddress((void**)&phi16, g_phi16);
    cudaGetSymbolAddress((void**)&W116, g_W116);
    cudaGetSymbolAddress((void**)&W216, g_W216);
    cudaGetSymbolAddress((void**)&dspT, g_dspT);
    cudaGetSymbolAddress((void**)&xin_h, g_xin_h); cudaGetSymbolAddress((void**)&xin_l, g_xin_l);
    cudaGetSymbolAddress((void**)&x2_h, g_x2_h);   cudaGetSymbolAddress((void**)&x2_l, g_x2_l);
    cudaGetSymbolAddress((void**)&y16, g_y16);
    cudaGetSymbolAddress((void**)&cmb, g_cmb);

    const size_t EXP = (size_t)Eq * Sq * Dq;

    // conversions (no transposes needed: B operands consumed K-major via ldmatrix.trans)
    convert_k<<<(Bq*Nq*Dq/4 + 255)/256, 256>>>(x, x16, (size_t)Bq*Nq*Dq/4);
    convert_k<<<(Dq*ESq/4 + 255)/256, 256>>>(phi, phi16, (size_t)Dq*ESq/4);
    convert_k<<<((size_t)Eq*Dq*Dq/4 + 255)/256, 256>>>(W1, W116, (size_t)Eq*Dq*Dq/4);
    convert_k<<<((size_t)Eq*Dq*Dq/4 + 255)/256, 256>>>(W2, W216, (size_t)Eq*Dq*Dq/4);

    // K1: w[b] = x[b] @ phi    M=2048 N=1024 K=1024
    mma_gemm_k<0,1,0><<<dim3(ESq/BN, Nq/BM, Bq), 256, SMEM_DYN>>>(
        x16, phi16, nullptr, nullptr, nullptr, w, nullptr, nullptr,
        Dq, Dq, ESq, ESq,
        (size_t)Nq*Dq, 0, (size_t)Nq*ESq, 1, 0,
        (size_t)64*Dq, (size_t)64*ESq);

    // fused dispatch softmax + transpose (2-pass)
    dispatch_fused_k<<<dim3(ESq/32, Bq), 256>>>(w, dspT);

    // K3: xin[b] = dsp[b]^T @ x[b]   M=1024(es) N=1024(d) K=2048(n)
    mma_gemm_k<0,0,1><<<dim3(Dq/BN, ESq/BM, Bq), 256, SMEM_DYN>>>(
        dspT, x16, nullptr, nullptr, nullptr, nullptr, xin_h, xin_l,
        Nq, Nq, Dq, Dq,
        (size_t)ESq*Nq, (size_t)Nq*Dq, (size_t)ESq*Dq, Bq, 0,
        (size_t)64*Nq, (size_t)64*Dq);

    // K4: h[e] = xin_e @ W1[e] + b1[e]   M=512 N=1024 K=1024, z=e
    mma_gemm_k<1,1,0><<<dim3(Dq/BN, (Bq*Sq)/BM, Eq), 256, SMEM_DYN>>>(
        xin_h, W116, b1, nullptr, nullptr, h, nullptr, nullptr,
        Dq, Dq, Dq, Dq,
        (size_t)Sq*Dq, (size_t)Dq*Dq, (size_t)Sq*Dq, Eq, (size_t)Dq,
        EXP, EXP);

    // LN + relu + residual
    ln_relu_k<<<Bq*Eq*Sq, 256>>>(h, xin_h, xin_l, g1, be1, x2_h, x2_l);

    // K6: y[e] = x2 + x2_e @ W2[e] + b2[e]  -> fp16 y directly (hi only)
    mma_gemm_k<3,0,2><<<dim3(Dq/BN, (Bq*Sq)/BM, Eq), 256, SMEM_DYN>>>(
        x2_h, W216, b2, x2_h, x2_l, nullptr, y16, nullptr,
        Dq, Dq, Dq, Dq,
        (size_t)Sq*Dq, (size_t)Dq*Dq, (size_t)Sq*Dq, Eq, (size_t)Dq,
        EXP, EXP);

    // combine softmax -> fp16
    row_softmax_k<<<Bq*Nq, 256>>>(w, cmb);

    // K8: out[b] = cmb[b] @ y[b]   M=2048 N=1024(d) K=1024(es)
    mma_gemm_k<0,1,0><<<dim3(Dq/BN, Nq/BM, Bq), 256, SMEM_DYN>>>(
        cmb, y16, nullptr, nullptr, nullptr, out, nullptr, nullptr,
        ESq, ESq, Dq, Dq,
        (size_t)Nq*ESq, EXP, (size_t)Nq*Dq, Bq, 0,
        (size_t)64*ESq, (size_t)64*Dq);
}

// round 9
// speedup vs baseline: 8.9259x; 1.0785x over previous
#include <cuda_runtime.h>
#include <cuda_fp16.h>
#include <math.h>
#include <stdint.h>

typedef __half fp16;

#define Bq   8
#define Nq   2048
#define Dq   1024
#define Eq   16
#define Sq   64
#define ESq  1024
#define EPSq 1e-5f

// ---------------- fp32 scratch ----------------
__device__ __align__(16) float g_w  [(size_t)Bq * Nq * ESq];
__device__ __align__(16) float g_h  [(size_t)Bq * Eq * Sq * Dq];

// ---------------- fp16 scratch ----------------
__device__ __align__(16) fp16 g_x16  [(size_t)Bq * Nq * Dq];
__device__ __align__(16) fp16 g_phi16[(size_t)Dq * ESq];
__device__ __align__(16) fp16 g_W116 [(size_t)Eq * Dq * Dq];
__device__ __align__(16) fp16 g_W216 [(size_t)Eq * Dq * Dq];
__device__ __align__(16) fp16 g_dspT [(size_t)Bq * ESq * Nq];
__device__ __align__(16) fp16 g_xin_h[(size_t)Bq * Eq * Sq * Dq], g_xin_l[(size_t)Bq * Eq * Sq * Dq];
__device__ __align__(16) fp16 g_x2_h [(size_t)Bq * Eq * Sq * Dq], g_x2_l [(size_t)Bq * Eq * Sq * Dq];
__device__ __align__(16) fp16 g_y16  [(size_t)Bq * Eq * Sq * Dq];
__device__ __align__(16) fp16 g_cmb  [(size_t)Bq * Nq * ESq];

// ================= mma.sync GEMM: A [M,K] row-major, B [K,N] row-major =================
#define BM 128
#define BN 128
#define BK 64
#define NSTG 3
#define PA 144                        // A row pitch bytes (64 fp16 + pad)
#define PB 272                        // B row pitch bytes (128 fp16 + pad)
#define A_BYTES (128 * PA)            // 18432
#define B_BYTES (64 * PB)             // 17408
#define OFF_A 0
#define OFF_B A_BYTES
#define STAGE (A_BYTES + B_BYTES)     // 35840
#define SMEM_DYN (NSTG * STAGE)       // 107520  (2 CTAs/SM)

__device__ __forceinline__ uint32_t s2u(const void* p) {
    uint32_t a;
    asm("{ .reg .u64 t; cvta.to.shared.u64 t, %1; cvt.u32.u64 %0, t; }" : "=r"(a) : "l"(p));
    return a;
}
__device__ __forceinline__ void cpa16(uint32_t dst, const void* src) {
    asm volatile("cp.async.cg.shared.global [%0], [%1], 16;" :: "r"(dst), "l"(src));
}
__device__ __forceinline__ void ldm_x4(uint32_t* r, uint32_t a) {
    asm volatile("ldmatrix.sync.aligned.m8n8.x4.shared.b16 {%0,%1,%2,%3}, [%4];"
                 : "=r"(r[0]), "=r"(r[1]), "=r"(r[2]), "=r"(r[3]) : "r"(a));
}
__device__ __forceinline__ void ldm_x4t(uint32_t* r, uint32_t a) {
    asm volatile("ldmatrix.sync.aligned.m8n8.x4.trans.shared.b16 {%0,%1,%2,%3}, [%4];"
                 : "=r"(r[0]), "=r"(r[1]), "=r"(r[2]), "=r"(r[3]) : "r"(a));
}
__device__ __forceinline__ void mma16816(float* c, const uint32_t* a, const uint32_t* b) {
    asm volatile(
        "mma.sync.aligned.m16n8k16.row.col.f32.f16.f16.f32 "
        "{%0,%1,%2,%3}, {%4,%5,%6,%7}, {%8,%9}, {%0,%1,%2,%3};"
        : "+f"(c[0]), "+f"(c[1]), "+f"(c[2]), "+f"(c[3])
        : "r"(a[0]), "r"(a[1]), "r"(a[2]), "r"(a[3]), "r"(b[0]), "r"(b[1]));
}

// C[z] = A[z] @ B[z%bMod].  A rows: (r>>6)*aRowBlk + (r&63)*lda; C likewise via cRowBlk.
// EPI: 0 none, 1 +bias[col], 3 +bias[col] + (resh+resl)[row,col]
// WC: write fp32 C.  SPLIT: 0 none, 1 fp16 hi+lo, 2 fp16 hi only.
template<int EPI, int WC, int SPLIT>
__global__ void __launch_bounds__(256, 2)
mma_gemm_k(const fp16* __restrict__ Ab, const fp16* __restrict__ Bb,
           const float* __restrict__ biasb,
           const fp16* __restrict__ reshb, const fp16* __restrict__ reslb,
           float* __restrict__ Cb, fp16* __restrict__ Chb, fp16* __restrict__ Clb,
           int K, int lda, int ldb, int ldc,
           size_t sA, size_t sB, size_t sC, int bMod, size_t sBias,
           size_t aRowBlk, size_t cRowBlk)
{
    extern __shared__ char sm[];
    const uint32_t sb = s2u(sm);
    const int tid = threadIdx.x, wid = tid >> 5, lane = tid & 31;
    const int z = blockIdx.z;

    const fp16* A = Ab + (size_t)z * sA;
    const fp16* B = Bb + (size_t)(z % bMod) * sB;

    const int m0 = blockIdx.y * BM;
    const int n0 = blockIdx.x * BN;

    // A: 1024 chunks (128 rows x 8), 4/thread
    size_t aoff[4]; uint32_t adst[4];
#pragma unroll
    for (int i = 0; i < 4; i++) {
        const int idx = tid + i * 256;
        const int row = idx >> 3, kc = idx & 7;
        const int m = m0 + row;
        aoff[i] = ((size_t)(m >> 6)) * aRowBlk + (size_t)(m & 63) * lda + kc * 8;
        adst[i] = (uint32_t)(row * PA + kc * 16);
    }
    // B: 1024 chunks (64 rows x 16), 4/thread
    size_t boff[4]; uint32_t bdst[4];
#pragma unroll
    for (int i = 0; i < 4; i++) {
        const int idx = tid + i * 256;
        const int row = idx >> 4, nc = idx & 15;
        boff[i] = (size_t)row * ldb + n0 + nc * 8;
        bdst[i] = (uint32_t)(row * PB + nc * 16);
    }

    auto load_stage = [&](int t) {
        const uint32_t stg = sb + (t % NSTG) * STAGE;
        const size_t ke = (size_t)t * BK;
#pragma unroll
        for (int i = 0; i < 4; i++) cpa16(stg + OFF_A + adst[i], A + aoff[i] + ke);
        const size_t kb = ke * ldb;
#pragma unroll
        for (int i = 0; i < 4; i++) cpa16(stg + OFF_B + bdst[i], B + boff[i] + kb);
        asm volatile("cp.async.commit_group;" ::: "memory");
    };

    const int wm = (wid >> 2) * 64;
    const int wn = (wid & 3) * 32;

    float acc[4][4][4];
#pragma unroll
    for (int mi = 0; mi < 4; mi++)
#pragma unroll
        for (int ni = 0; ni < 4; ni++)
#pragma unroll
            for (int q = 0; q < 4; q++) acc[mi][ni][q] = 0.f;

    const int nt = K / BK;
    load_stage(0);
    if (nt > 1) load_stage(1);

    for (int t = 0; t < nt; t++) {
        if (t + 1 < nt) asm volatile("cp.async.wait_group 1;" ::: "memory");
        else            asm volatile("cp.async.wait_group 0;" ::: "memory");
        __syncthreads();
        if (t + 2 < nt) load_stage(t + 2);

        const uint32_t stg = sb + (t % NSTG) * STAGE;
#pragma unroll
        for (int ks = 0; ks < 4; ks++) {
            const int kb = ks * 16;
            uint32_t ah[4][4], bh[2][4];
#pragma unroll
            for (int mi = 0; mi < 4; mi++) {
                const uint32_t ao =
                    (uint32_t)((wm + mi * 16 + (lane & 15)) * PA + (kb + (lane >> 4) * 8) * 2);
                ldm_x4(ah[mi], stg + OFF_A + ao);
            }
#pragma unroll
            for (int nj = 0; nj < 2; nj++) {
                const uint32_t bo =
                    (uint32_t)((kb + (lane & 15)) * PB + (wn + nj * 16 + (lane >> 4) * 8) * 2);
                ldm_x4t(bh[nj], stg + OFF_B + bo);
            }
#pragma unroll
            for (int mi = 0; mi < 4; mi++)
#pragma unroll
                for (int ni = 0; ni < 4; ni++)
                    mma16816(acc[mi][ni], ah[mi], &bh[ni >> 1][(ni & 1) * 2]);
        }
    }

    // ---------------- epilogue ----------------
    float*       C  = WC ? (Cb + (size_t)z * sC) : nullptr;
    fp16*        Ch = SPLIT ? (Chb + (size_t)z * sC) : nullptr;
    fp16*        Cl = (SPLIT == 1) ? (Clb + (size_t)z * sC) : nullptr;
    const float* bias = (EPI >= 1) ? (biasb + (size_t)(z % bMod) * sBias) : nullptr;
    const fp16*  resh = (EPI == 3) ? (reshb + (size_t)z * sC) : nullptr;
    const fp16*  resl = (EPI == 3) ? (reslb + (size_t)z * sC) : nullptr;

#pragma unroll
    for (int mi = 0; mi < 4; mi++) {
        const int mA = m0 + wm + mi * 16 + (lane >> 2);
        const int mB = mA + 8;
        const size_t coA = ((size_t)(mA >> 6)) * cRowBlk + (size_t)(mA & 63) * ldc;
        const size_t coB = ((size_t)(mB >> 6)) * cRowBlk + (size_t)(mB & 63) * ldc;
#pragma unroll
        for (int ni = 0; ni < 4; ni++) {
            const int col = n0 + wn + ni * 8 + (lane & 3) * 2;
            float2 v0 = make_float2(acc[mi][ni][0], acc[mi][ni][1]);
            float2 v1 = make_float2(acc[mi][ni][2], acc[mi][ni][3]);
            if (EPI >= 1) {
                const float2 bb = *reinterpret_cast<const float2*>(&bias[col]);
                v0.x += bb.x; v0.y += bb.y; v1.x += bb.x; v1.y += bb.y;
            }
            if (EPI == 3) {
                const __half2 hA = *reinterpret_cast<const __half2*>(&resh[coA + col]);
                const __half2 lA = *reinterpret_cast<const __half2*>(&resl[coA + col]);
                const __half2 hB = *reinterpret_cast<const __half2*>(&resh[coB + col]);
                const __half2 lB = *reinterpret_cast<const __half2*>(&resl[coB + col]);
                v0.x += __half2float(hA.x) + __half2float(lA.x);
                v0.y += __half2float(hA.y) + __half2float(lA.y);
                v1.x += __half2float(hB.x) + __half2float(lB.x);
                v1.y += __half2float(hB.y) + __half2float(lB.y);
            }
            if (WC) {
                *reinterpret_cast<float2*>(&C[coA + col]) = v0;
                *reinterpret_cast<float2*>(&C[coB + col]) = v1;
            }
            if (SPLIT) {
                fp16 h0 = __float2half_rn(v0.x), h1 = __float2half_rn(v0.y);
                fp16 h2 = __float2half_rn(v1.x), h3 = __float2half_rn(v1.y);
                *reinterpret_cast<__half2*>(&Ch[coA + col]) = __halves2half2(h0, h1);
                *reinterpret_cast<__half2*>(&Ch[coB + col]) = __halves2half2(h2, h3);
                if (SPLIT == 1) {
                    *reinterpret_cast<__half2*>(&Cl[coA + col]) = __halves2half2(
                        __float2half_rn(v0.x - __half2float(h0)),
                        __float2half_rn(v0.y - __half2float(h1)));
                    *reinterpret_cast<__half2*>(&Cl[coB + col]) = __halves2half2(
                        __float2half_rn(v1.x - __half2float(h2)),
                        __float2half_rn(v1.y - __half2float(h3)));
                }
            }
        }
    }
}

// ====== fused fp32->fp16 conversion of x, phi, W1, W2 in ONE kernel ======
#define N4_X   ((size_t)Bq * Nq * Dq / 4)        // 2M float4
#define N4_PHI ((size_t)Dq * ESq / 4)            // 256K
#define N4_W   ((size_t)Eq * Dq * Dq / 4)        // 4M each
#define N4_TOT (N4_X + N4_PHI + 2 * N4_W)

__global__ void convert_all_k(const float* __restrict__ x, const float* __restrict__ phi,
                              const float* __restrict__ W1, const float* __restrict__ W2,
                              fp16* __restrict__ ox, fp16* __restrict__ ophi,
                              fp16* __restrict__ oW1, fp16* __restrict__ oW2)
{
    size_t i = (size_t)blockIdx.x * blockDim.x + threadIdx.x;
    if (i >= N4_TOT) return;
    const float* in; fp16* o;
    if (i < N4_X)                      { in = x;   o = ox;   }
    else if (i < N4_X + N4_PHI)        { i -= N4_X;          in = phi; o = ophi; }
    else if (i < N4_X + N4_PHI + N4_W) { i -= N4_X + N4_PHI; in = W1;  o = oW1;  }
    else                               { i -= N4_X + N4_PHI + N4_W; in = W2; o = oW2; }
    const float4 v = reinterpret_cast<const float4*>(in)[i];
    reinterpret_cast<__half2*>(o)[2 * i] =
        __halves2half2(__float2half_rn(v.x), __float2half_rn(v.y));
    reinterpret_cast<__half2*>(o)[2 * i + 1] =
        __halves2half2(__float2half_rn(v.z), __float2half_rn(v.w));
}

// ====== fused dispatch softmax (over tokens) + transpose -> fp16, 2-pass ======
__global__ void dispatch_fused_k(const float* __restrict__ w, fp16* __restrict__ oh)
{
    const int b = blockIdx.y, lane = threadIdx.x & 31, grp = threadIdx.x >> 5;
    const int col0 = blockIdx.x * 32;
    const float* p = w + (size_t)b * Nq * ESq + col0;

    __shared__ float redm[8][33], reds[8][33];
    __shared__ float mcol[32], icol[32];
    __shared__ float t[32][33];

    float m = -1e30f, s = 0.f;
    for (int n = grp; n < Nq; n += 8) {
        const float v = p[(size_t)n * ESq + lane];
        const float nm = fmaxf(m, v);
        s = s * __expf(m - nm) + __expf(v - nm);
        m = nm;
    }
    redm[grp][lane] = m; reds[grp][lane] = s;
    __syncthreads();
    if (grp == 0) {
        float M = redm[0][lane];
#pragma unroll
        for (int g = 1; g < 8; g++) M = fmaxf(M, redm[g][lane]);
        float S = 0.f;
#pragma unroll
        for (int g = 0; g < 8; g++) S += reds[g][lane] * __expf(redm[g][lane] - M);
        mcol[lane] = M;
        icol[lane] = 1.f / S;
    }
    __syncthreads();

    const size_t obase = (size_t)b * ESq * Nq;
    for (int n0 = 0; n0 < Nq; n0 += 32) {
#pragma unroll
        for (int i = 0; i < 4; i++) {
            const int r = grp * 4 + i;
            t[r][lane] = p[(size_t)(n0 + r) * ESq + lane];
        }
        __syncthreads();
#pragma unroll
        for (int i = 0; i < 4; i++) {
            const int cc = grp * 4 + i;
            const float val = __expf(t[lane][cc] - mcol[cc]) * icol[cc];
            oh[obase + (size_t)(col0 + cc) * Nq + n0 + lane] = __float2half_rn(val);
        }
        __syncthreads();
    }
}

// ================= combine softmax (row) -> fp16 =================
__global__ void row_softmax_k(const float* __restrict__ w, fp16* __restrict__ oh)
{
    const size_t r = blockIdx.x;
    const float* p = w + r * ESq;
    const int tid = threadIdx.x;
    __shared__ float buf[256];

    float v[4];
    float mx = -1e30f;
#pragma unroll
    for (int j = 0; j < 4; j++) { v[j] = p[tid + 256 * j]; mx = fmaxf(mx, v[j]); }
    buf[tid] = mx;
    __syncthreads();
    for (int off = 128; off > 0; off >>= 1) {
        if (tid < off) buf[tid] = fmaxf(buf[tid], buf[tid + off]);
        __syncthreads();
    }
    const float m = buf[0];
    __syncthreads();
    float s = 0.f;
#pragma unroll
    for (int j = 0; j < 4; j++) { v[j] = __expf(v[j] - m); s += v[j]; }
    buf[tid] = s;
    __syncthreads();
    for (int off = 128; off > 0; off >>= 1) {
        if (tid < off) buf[tid] += buf[tid + off];
        __syncthreads();
    }
    const float inv = 1.f / buf[0];
#pragma unroll
    for (int j = 0; j < 4; j++)
        oh[r * ESq + tid + 256 * j] = __float2half_rn(v[j] * inv);
}

// ===== LN + relu + residual: x2 = (xinH+xinL) + relu(LN(h)); emit fp16 hi/lo =====
__global__ void ln_relu_k(const float* __restrict__ h,
                          const fp16* __restrict__ xh, const fp16* __restrict__ xl,
                          const float* __restrict__ g, const float* __restrict__ be,
                          fp16* __restrict__ oh, fp16* __restrict__ ol)
{
    const int r = blockIdx.x;
    const int e = (r / Sq) % Eq;
    const float* hr = h + (size_t)r * Dq;
    const int tid = threadIdx.x;
    __shared__ float rs[256], rs2[256];

    float v[4];
    float s = 0.f, s2 = 0.f;
#pragma unroll
    for (int j = 0; j < 4; j++) {
        v[j] = hr[tid + 256 * j];
        s += v[j]; s2 += v[j] * v[j];
    }
    rs[tid] = s; rs2[tid] = s2;
    __syncthreads();
    for (int off = 128; off > 0; off >>= 1) {
        if (tid < off) { rs[tid] += rs[tid + off]; rs2[tid] += rs2[tid + off]; }
        __syncthreads();
    }
    const float mean = rs[0] * (1.f / Dq);
    const float var  = rs2[0] * (1.f / Dq) - mean * mean;
    const float rstd = rsqrtf(var + EPSq);

#pragma unroll
    for (int j = 0; j < 4; j++) {
        const int d = tid + 256 * j;
        const size_t o = (size_t)r * Dq + d;
        const float xr = __half2float(xh[o]) + __half2float(xl[o]);
        const float ln = (v[j] - mean) * rstd * g[(size_t)e * Dq + d] + be[(size_t)e * Dq + d];
        const float val = xr + fmaxf(ln, 0.f);
        fp16 hh = __float2half_rn(val);
        oh[o] = hh;
        ol[o] = __float2half_rn(val - __half2float(hh));
    }
}

// ================= launch =================
extern "C" void kernel_launch(void* const* d_in, const int* in_sizes, int n_in,
                              void* d_out, int out_size)
{
    const float* x   = (const float*)d_in[0];
    const float* phi = (const float*)d_in[1];
    const float* W1  = (const float*)d_in[2];
    const float* b1  = (const float*)d_in[3];
    const float* g1  = (const float*)d_in[4];
    const float* be1 = (const float*)d_in[5];
    const float* W2  = (const float*)d_in[6];
    const float* b2  = (const float*)d_in[7];
    float* out = (float*)d_out;

    cudaFuncSetAttribute(mma_gemm_k<0,1,0>, cudaFuncAttributeMaxDynamicSharedMemorySize, SMEM_DYN);
    cudaFuncSetAttribute(mma_gemm_k<0,0,1>, cudaFuncAttributeMaxDynamicSharedMemorySize, SMEM_DYN);
    cudaFuncSetAttribute(mma_gemm_k<1,1,0>, cudaFuncAttributeMaxDynamicSharedMemorySize, SMEM_DYN);
    cudaFuncSetAttribute(mma_gemm_k<3,0,2>, cudaFuncAttributeMaxDynamicSharedMemorySize, SMEM_DYN);

    float *w, *h;
    cudaGetSymbolAddress((void**)&w, g_w);
    cudaGetSymbolAddress((void**)&h, g_h);

    fp16 *x16,*phi16,*W116,*W216,*dspT,*xin_h,*xin_l,*x2_h,*x2_l,*y16,*cmb;
    cudaGetSymbolAddress((void**)&x16, g_x16);
    cudaGetSymbolAddress((void**)&phi16, g_phi16);
    cudaGetSymbolAddress((void**)&W116, g_W116);
    cudaGetSymbolAddress((void**)&W216, g_W216);
    cudaGetSymbolAddress((void**)&dspT, g_dspT);
    cudaGetSymbolAddress((void**)&xin_h, g_xin_h); cudaGetSymbolAddress((void**)&xin_l, g_xin_l);
    cudaGetSymbolAddress((void**)&x2_h, g_x2_h);   cudaGetSymbolAddress((void**)&x2_l, g_x2_l);
    cudaGetSymbolAddress((void**)&y16, g_y16);
    cudaGetSymbolAddress((void**)&cmb, g_cmb);

    const size_t EXP = (size_t)Eq * Sq * Dq;

    // single fused conversion pass
    convert_all_k<<<(int)((N4_TOT + 255) / 256), 256>>>(x, phi, W1, W2, x16, phi16, W116, W216);

    // K1: w[b] = x[b] @ phi    M=2048 N=1024 K=1024
    mma_gemm_k<0,1,0><<<dim3(ESq/BN, Nq/BM, Bq), 256, SMEM_DYN>>>(
        x16, phi16, nullptr, nullptr, nullptr, w, nullptr, nullptr,
        Dq, Dq, ESq, ESq,
        (size_t)Nq*Dq, 0, (size_t)Nq*ESq, 1, 0,
        (size_t)64*Dq, (size_t)64*ESq);

    // fused dispatch softmax + transpose (2-pass)
    dispatch_fused_k<<<dim3(ESq/32, Bq), 256>>>(w, dspT);

    // K3: xin[b] = dsp[b]^T @ x[b]   M=1024(es) N=1024(d) K=2048(n)
    mma_gemm_k<0,0,1><<<dim3(Dq/BN, ESq/BM, Bq), 256, SMEM_DYN>>>(
        dspT, x16, nullptr, nullptr, nullptr, nullptr, xin_h, xin_l,
        Nq, Nq, Dq, Dq,
        (size_t)ESq*Nq, (size_t)Nq*Dq, (size_t)ESq*Dq, Bq, 0,
        (size_t)64*Nq, (size_t)64*Dq);

    // K4: h[e] = xin_e @ W1[e] + b1[e]   M=512 N=1024 K=1024, z=e
    mma_gemm_k<1,1,0><<<dim3(Dq/BN, (Bq*Sq)/BM, Eq), 256, SMEM_DYN>>>(
        xin_h, W116, b1, nullptr, nullptr, h, nullptr, nullptr,
        Dq, Dq, Dq, Dq,
        (size_t)Sq*Dq, (size_t)Dq*Dq, (size_t)Sq*Dq, Eq, (size_t)Dq,
        EXP, EXP);

    // LN + relu + residual
    ln_relu_k<<<Bq*Eq*Sq, 256>>>(h, xin_h, xin_l, g1, be1, x2_h, x2_l);

    // K6: y[e] = x2 + x2_e @ W2[e] + b2[e]  -> fp16 y directly
    mma_gemm_k<3,0,2><<<dim3(Dq/BN, (Bq*Sq)/BM, Eq), 256, SMEM_DYN>>>(
        x2_h, W216, b2, x2_h, x2_l, nullptr, y16, nullptr,
        Dq, Dq, Dq, Dq,
        (size_t)Sq*Dq, (size_t)Dq*Dq, (size_t)Sq*Dq, Eq, (size_t)Dq,
        EXP, EXP);

    // combine softmax -> fp16
    row_softmax_k<<<Bq*Nq, 256>>>(w, cmb);

    // K8: out[b] = cmb[b] @ y[b]   M=2048 N=1024(d) K=1024(es)
    mma_gemm_k<0,1,0><<<dim3(Dq/BN, Nq/BM, Bq), 256, SMEM_DYN>>>(
        cmb, y16, nullptr, nullptr, nullptr, out, nullptr, nullptr,
        ESq, ESq, Dq, Dq,
        (size_t)Nq*ESq, EXP, (size_t)Nq*Dq, Bq, 0,
        (size_t)64*ESq, (size_t)64*Dq);
}